// round 10
// baseline (speedup 1.0000x reference)
#include <cuda_runtime.h>
#include <cstdint>
#include <cstddef>

// ---------------- problem constants ----------------
#define BB 2
#define CC 256
#define HH 128
#define WW 128
#define HW 16384
#define MPIX 32768
#define NCLS 80
#define NMS_CAND 1000
#define MAX_DET 100
#define KB 32
#define STG (KB * 132)     // floats per stage per array
#define NPANEL (256 / KB)  // 8
#define STG16 (16 * 132)

// ---------------- scratch ----------------
// activations kept TRANSPOSED: [256][MPIX]
__device__ float g_bA[3][(size_t)CC * MPIX];
__device__ float g_bB[3][(size_t)CC * MPIX];
__device__ float g_WT[15 * 256 * 256];          // pre-transposed weights [k][n]
__device__ float g_score[MPIX];
__device__ int   g_label[MPIX];
__device__ float g_boxes[(size_t)MPIX * 4];
__device__ float g_cand_sc[BB * NMS_CAND];
__device__ int   g_cand_lab[BB * NMS_CAND];
__device__ float g_cand_box[BB * NMS_CAND * 4];
__device__ unsigned g_mask[(size_t)BB * NMS_CAND * 32];
__device__ unsigned g_keep[BB * 32];

// ---------------- helpers ----------------
__device__ __forceinline__ unsigned smem_addr(const void* p) {
    return (unsigned)__cvta_generic_to_shared(p);
}
__device__ __forceinline__ void cpasync16(unsigned dst, const float* src) {
    asm volatile("cp.async.cg.shared.global [%0], [%1], 16;\n" :: "r"(dst), "l"(src));
}
__device__ __forceinline__ void cp_commit() {
    asm volatile("cp.async.commit_group;\n" ::: "memory");
}
template <int N>
__device__ __forceinline__ void cp_wait() {
    asm volatile("cp.async.wait_group %0;\n" :: "n"(N) : "memory");
}
__device__ __forceinline__ void ffma2(unsigned long long& d, unsigned long long a, unsigned long long b) {
    asm("fma.rn.f32x2 %0, %1, %2, %0;" : "+l"(d) : "l"(a), "l"(b));
}
__device__ __forceinline__ unsigned long long dup2(float x) {
    unsigned long long r;
    asm("mov.b64 %0, {%1, %1};" : "=l"(r) : "f"(x));
    return r;
}
__device__ __forceinline__ void unpack2(unsigned long long v, float& lo, float& hi) {
    asm("mov.b64 {%0, %1}, %2;" : "=f"(lo), "=f"(hi) : "l"(v));
}
__device__ __forceinline__ float sigmoidf_(float x) { return 1.f / (1.f + expf(-x)); }

// ---------------- weight transpose: W[n][k] -> WT[k][n], 15 matrices ----------------
__global__ void wtrans_k(const float* __restrict__ cwin, const float* __restrict__ owin,
                         const float* __restrict__ bwin, const float* __restrict__ cwh,
                         const float* __restrict__ owh, const float* __restrict__ bwh) {
    __shared__ float t[32][33];
    int z = blockIdx.z;
    const float* src;
    if (z < 3) src = z == 0 ? cwin : (z == 1 ? owin : bwin);
    else {
        int h = (z - 3) >> 2, li = (z - 3) & 3;
        const float* hh = h == 0 ? cwh : (h == 1 ? owh : bwh);
        src = hh + (size_t)li * 65536;
    }
    float* dst = g_WT + (size_t)z * 65536;
    int x0 = blockIdx.x * 32, y0 = blockIdx.y * 32;
    int tx = threadIdx.x, ty = threadIdx.y;   // (32,8)
    #pragma unroll
    for (int i = 0; i < 32; i += 8)
        t[ty + i][tx] = src[(size_t)(y0 + ty + i) * 256 + x0 + tx];
    __syncthreads();
    #pragma unroll
    for (int i = 0; i < 32; i += 8)
        dst[(size_t)(x0 + ty + i) * 256 + y0 + tx] = t[tx][ty + i];
}

// ---------------- 3-head fp32 GEMM (R7 inner loop), direct-feat l0 path ----------------
// A: [256][MPIX] k-major (or feat [B][256][HW] when l0=1), W: [256][256] k-major.
// O[n][m] = sum_k A[k][m]*W[k][n] + bias[n] (+A[n][m] residual when l0=0)
__global__ void __launch_bounds__(256, 2) gemm3_k(
    const float* __restrict__ A0, const float* __restrict__ A1, const float* __restrict__ A2,
    const float* __restrict__ W0, const float* __restrict__ W1, const float* __restrict__ W2,
    const float* __restrict__ c0, const float* __restrict__ c1, const float* __restrict__ c2,
    float* __restrict__ O0, float* __restrict__ O1, float* __restrict__ O2,
    int l0)
{
    extern __shared__ __align__(16) float sm[];
    float* As = sm;              // [3][KB][132]
    float* Bs = sm + 3 * STG;    // [3][KB][132]

    const int head = blockIdx.z;
    const float* A    = head == 0 ? A0 : head == 1 ? A1 : A2;
    const float* Wt   = head == 0 ? W0 : head == 1 ? W1 : W2;
    const float* bias = head == 0 ? c0 : head == 1 ? c1 : c2;
    float* Cout       = head == 0 ? O0 : head == 1 ? O1 : O2;

    const int m0 = blockIdx.y * 128;
    const int n0 = blockIdx.x * 128;
    const int tid = threadIdx.x;
    const int tx = tid & 15, ty = tid >> 4;

    const float* Abase;
    size_t Astride;
    if (l0) {
        int b = m0 >> 14;
        Abase = A + (size_t)b * CC * HW + (m0 & (HW - 1));
        Astride = HW;
    } else {
        Abase = A + m0;
        Astride = MPIX;
    }

    auto load_panel = [&](int p, int s) {
        float* Asd = As + s * STG;
        float* Bsd = Bs + s * STG;
        #pragma unroll
        for (int lq = 0; lq < 4; lq++) {
            int idx = tid + lq * 256;
            int k = idx >> 5, c4 = idx & 31;
            cpasync16(smem_addr(&Asd[k * 132 + c4 * 4]),
                      Abase + (size_t)(p * KB + k) * Astride + c4 * 4);
        }
        #pragma unroll
        for (int lq = 0; lq < 4; lq++) {
            int idx = tid + lq * 256;
            int k = idx >> 5, c4 = idx & 31;
            cpasync16(smem_addr(&Bsd[k * 132 + c4 * 4]),
                      Wt + (size_t)(p * KB + k) * 256 + n0 + c4 * 4);
        }
        cp_commit();
    };

    unsigned long long acc2[8][4];   // [n-slot][m-pair]
    #pragma unroll
    for (int j = 0; j < 8; j++)
        #pragma unroll
        for (int q = 0; q < 4; q++) acc2[j][q] = 0ull;

    load_panel(0, 0);
    load_panel(1, 1);

    #pragma unroll 1
    for (int p = 0; p < NPANEL; p++) {
        if (p < NPANEL - 1) cp_wait<1>(); else cp_wait<0>();
        __syncthreads();
        if (p + 2 < NPANEL) load_panel(p + 2, (p + 2) % 3);
        const float* Asd = As + (p % 3) * STG;
        const float* Bsd = Bs + (p % 3) * STG;
        #pragma unroll 8
        for (int kk = 0; kk < KB; kk++) {
            ulonglong2 aA = *(const ulonglong2*)&Asd[kk * 132 + 4 * ty];        // m: 4ty..4ty+3
            ulonglong2 aB = *(const ulonglong2*)&Asd[kk * 132 + 64 + 4 * ty];   // m: 64+4ty..
            float4 bb0 = *(const float4*)&Bsd[kk * 132 + 4 * tx];               // n: 4tx..4tx+3
            float4 bb1 = *(const float4*)&Bsd[kk * 132 + 64 + 4 * tx];          // n: 64+4tx..
            unsigned long long am[4] = {aA.x, aA.y, aB.x, aB.y};
            unsigned long long bd[8] = {dup2(bb0.x), dup2(bb0.y), dup2(bb0.z), dup2(bb0.w),
                                        dup2(bb1.x), dup2(bb1.y), dup2(bb1.z), dup2(bb1.w)};
            #pragma unroll
            for (int j = 0; j < 8; j++)
                #pragma unroll
                for (int q = 0; q < 4; q++)
                    ffma2(acc2[j][q], am[q], bd[j]);
        }
    }

    // epilogue: write O[n][m] (transposed); residual read also [n][m] (skip for l0)
    #pragma unroll
    for (int j = 0; j < 8; j++) {
        int n = n0 + ((j < 4) ? (4 * tx + j) : (64 + 4 * tx + (j - 4)));
        float bv = bias[n];
        float f0, f1, f2, f3, h0, h1, h2, h3;
        unpack2(acc2[j][0], f0, f1);
        unpack2(acc2[j][1], f2, f3);
        unpack2(acc2[j][2], h0, h1);
        unpack2(acc2[j][3], h2, h3);
        float4 v0 = make_float4(f0 + bv, f1 + bv, f2 + bv, f3 + bv);
        float4 v1 = make_float4(h0 + bv, h1 + bv, h2 + bv, h3 + bv);
        if (!l0) {
            float4 r0 = *(const float4*)(A + (size_t)n * MPIX + m0 + 4 * ty);
            float4 r1 = *(const float4*)(A + (size_t)n * MPIX + m0 + 64 + 4 * ty);
            v0.x += r0.x; v0.y += r0.y; v0.z += r0.z; v0.w += r0.w;
            v1.x += r1.x; v1.y += r1.y; v1.z += r1.z; v1.w += r1.w;
        }
        *(float4*)(Cout + (size_t)n * MPIX + m0 + 4 * ty) = v0;
        *(float4*)(Cout + (size_t)n * MPIX + m0 + 64 + 4 * ty) = v1;
    }
}

// ---------------- fused out-layers + decode ----------------
__global__ void __launch_bounds__(256) outdec_k(
    const float* __restrict__ Acls, const float* __restrict__ Aobj, const float* __restrict__ Abox,
    const float* __restrict__ cw, const float* __restrict__ cb,
    const float* __restrict__ ow, const float* __restrict__ ob,
    const float* __restrict__ bw, const float* __restrict__ bbx)
{
    extern __shared__ __align__(16) float sm[];
    float* As_c = sm;
    float* As_b = sm + STG16;
    float* As_o = sm + 2 * STG16;
    float* Bsw  = sm + 3 * STG16;
    float* sbias = sm + 3 * STG16 + 1600;
    float* slog = sm + 3 * STG16 + 1712;

    const int m0 = blockIdx.x * 128;
    const int tid = threadIdx.x;
    const int tx = tid & 15, ty = tid >> 4;

    if (tid < 96) {
        float bv = 0.f;
        if (tid < 80) bv = cb[tid];
        else if (tid < 84) bv = bbx[tid - 80];
        else if (tid == 84) bv = ob[0];
        sbias[tid] = bv;
    }

    float acc[8][6];
    #pragma unroll
    for (int i = 0; i < 8; i++)
        #pragma unroll
        for (int j = 0; j < 6; j++) acc[i][j] = 0.f;

    #pragma unroll 1
    for (int p = 0; p < 16; p++) {
        __syncthreads();
        #pragma unroll
        for (int lq = 0; lq < 2; lq++) {
            int idx = tid + lq * 256;
            int k = idx >> 5, c4 = idx & 31;
            size_t off = (size_t)(p * 16 + k) * MPIX + m0 + c4 * 4;
            *(float4*)&As_c[k * 132 + c4 * 4] = *(const float4*)(Acls + off);
            *(float4*)&As_b[k * 132 + c4 * 4] = *(const float4*)(Abox + off);
            *(float4*)&As_o[k * 132 + c4 * 4] = *(const float4*)(Aobj + off);
        }
        #pragma unroll
        for (int lq = 0; lq < 6; lq++) {
            int idx = tid + lq * 256;
            int k = idx & 15, slot = idx >> 4;
            float v = 0.f;
            if (slot < 80)       v = cw[slot * 256 + p * 16 + k];
            else if (slot < 84)  v = bw[(slot - 80) * 256 + p * 16 + k];
            else if (slot == 84) v = ow[p * 16 + k];
            Bsw[k * 100 + slot] = v;
        }
        __syncthreads();

        const float* As_x = (tx < 4) ? As_b : (tx == 4 ? As_o : As_c);
        #pragma unroll
        for (int kk = 0; kk < 16; kk++) {
            float4 a0 = *(const float4*)&As_c[kk * 132 + ty * 8];
            float4 a1 = *(const float4*)&As_c[kk * 132 + ty * 8 + 4];
            float4 x0 = *(const float4*)&As_x[kk * 132 + ty * 8];
            float4 x1 = *(const float4*)&As_x[kk * 132 + ty * 8 + 4];
            float ac[8] = {a0.x, a0.y, a0.z, a0.w, a1.x, a1.y, a1.z, a1.w};
            float ax[8] = {x0.x, x0.y, x0.z, x0.w, x1.x, x1.y, x1.z, x1.w};
            float b[6];
            #pragma unroll
            for (int j = 0; j < 6; j++) b[j] = Bsw[kk * 100 + tx + 16 * j];
            #pragma unroll
            for (int i = 0; i < 8; i++) {
                #pragma unroll
                for (int j = 0; j < 5; j++)
                    acc[i][j] = fmaf(ac[i], b[j], acc[i][j]);
                acc[i][5] = fmaf(ax[i], b[5], acc[i][5]);
            }
        }
    }

    __syncthreads();
    #pragma unroll
    for (int i = 0; i < 8; i++)
        #pragma unroll
        for (int j = 0; j < 6; j++) {
            int col = tx + 16 * j;
            slog[(ty * 8 + i) * 97 + col] = acc[i][j] + sbias[col];
        }
    __syncthreads();

    if (tid < 128) {
        const float* lg = &slog[tid * 97];
        float objp = sigmoidf_(lg[84]);
        float best = -1.f; int bl = 0;
        #pragma unroll 4
        for (int c = 0; c < NCLS; c++) {
            float pr = sigmoidf_(lg[c]) * objp;
            if (pr > best) { best = pr; bl = c; }
        }
        int n = m0 + tid;
        g_score[n] = best;
        g_label[n] = bl;
        int hw = n & (HW - 1);
        int h = hw >> 7, w = hw & 127;
        float px = (w + 0.5f) * 8.f;
        float py = (h + 0.5f) * 8.f;
        float l = expf(lg[80]) * 8.f;
        float t = expf(lg[81]) * 8.f;
        float r = expf(lg[82]) * 8.f;
        float d = expf(lg[83]) * 8.f;
        g_boxes[(size_t)n * 4 + 0] = px - l;
        g_boxes[(size_t)n * 4 + 1] = py - t;
        g_boxes[(size_t)n * 4 + 2] = px + r;
        g_boxes[(size_t)n * 4 + 3] = py + d;
    }
}

// ---------------- exact top-1000: warp-aggregated histograms + compact + bitonic ----------------
__global__ void topk_k() {
    __shared__ int hist[256];
    __shared__ int s_b1, s_n1, s_thr, s_cnt;
    __shared__ unsigned long long skey[4096];
    int b = blockIdx.x;
    int tid = threadIdx.x;   // 1024
    int lane = tid & 31;

    if (tid < 256) hist[tid] = 0;
    __syncthreads();
    for (int i = tid; i < HW; i += 1024) {
        unsigned u = __float_as_uint(g_score[b * HW + i]);
        int bin = u >> 24;
        unsigned mm = __match_any_sync(0xffffffffu, bin);
        if (lane == (__ffs(mm) - 1)) atomicAdd(&hist[bin], __popc(mm));
    }
    __syncthreads();
    if (tid == 0) {
        int acc = 0; int bin = 255;
        for (; bin > 0; bin--) { if (acc + hist[bin] >= NMS_CAND) break; acc += hist[bin]; }
        s_b1 = bin; s_n1 = acc;
    }
    __syncthreads();
    int b1 = s_b1, n1 = s_n1;
    if (tid < 256) hist[tid] = 0;
    __syncthreads();
    for (int i = tid; i < HW; i += 1024) {
        unsigned u = __float_as_uint(g_score[b * HW + i]);
        bool sel = ((int)(u >> 24) == b1);
        unsigned active = __ballot_sync(0xffffffffu, sel);
        if (sel) {
            int bin2 = (u >> 16) & 255;
            unsigned mm = __match_any_sync(active, bin2);
            if (lane == (__ffs(mm) - 1)) atomicAdd(&hist[bin2], __popc(mm));
        }
    }
    __syncthreads();
    if (tid == 0) {
        int acc = n1; int bin = 255;
        for (; bin > 0; bin--) { if (acc + hist[bin] >= NMS_CAND) break; acc += hist[bin]; }
        s_thr = (b1 << 8) | bin;
        s_cnt = 0;
    }
    __syncthreads();
    unsigned thr = (unsigned)s_thr;
    for (int i = tid; i < HW; i += 1024) {
        unsigned u = __float_as_uint(g_score[b * HW + i]);
        bool pass = (u >> 16) >= thr;
        unsigned bal = __ballot_sync(0xffffffffu, pass);
        int base = 0;
        if (lane == 0 && bal) base = atomicAdd(&s_cnt, __popc(bal));
        base = __shfl_sync(0xffffffffu, base, 0);
        if (pass) {
            int pos = base + __popc(bal & ((1u << lane) - 1u));
            if (pos < 4096)
                skey[pos] = ((unsigned long long)(~u) << 32) | (unsigned)i;
        }
    }
    __syncthreads();
    int cnt = s_cnt < 4096 ? s_cnt : 4096;
    for (int i = tid; i < 4096; i += 1024)
        if (i >= cnt) skey[i] = 0xFFFFFFFFFFFFFFFFull;
    __syncthreads();

    for (int k = 2; k <= 4096; k <<= 1) {
        for (int j = k >> 1; j > 0; j >>= 1) {
            #pragma unroll
            for (int l = 0; l < 4; l++) {
                int i = tid + l * 1024;
                int ixj = i ^ j;
                if (ixj > i) {
                    bool up = ((i & k) == 0);
                    unsigned long long a = skey[i], c = skey[ixj];
                    if (up ? (a > c) : (a < c)) { skey[i] = c; skey[ixj] = a; }
                }
            }
            __syncthreads();
        }
    }

    if (tid < NMS_CAND) {
        unsigned long long key = skey[tid];
        int idx = (int)(unsigned)key;
        float s = __uint_as_float(~(unsigned)(key >> 32));
        int g = b * HW + idx;
        int dst = b * NMS_CAND + tid;
        g_cand_sc[dst] = s;
        g_cand_lab[dst] = g_label[g];
        #pragma unroll
        for (int q = 0; q < 4; q++)
            g_cand_box[dst * 4 + q] = g_boxes[(size_t)g * 4 + q];
    }
}

// ---------------- NMS ----------------
__global__ void nms_mask_k() {
    int i = blockIdx.x;
    int b = blockIdx.y;
    int j = threadIdx.x;
    const float* bi = &g_cand_box[(b * NMS_CAND + i) * 4];
    float ix1 = bi[0], iy1 = bi[1], ix2 = bi[2], iy2 = bi[3];
    float ai = fmaxf(ix2 - ix1, 0.f) * fmaxf(iy2 - iy1, 0.f);
    bool pred = false;
    if (j < NMS_CAND && j > i) {
        const float* bj = &g_cand_box[(b * NMS_CAND + j) * 4];
        float aj = fmaxf(bj[2] - bj[0], 0.f) * fmaxf(bj[3] - bj[1], 0.f);
        float xx1 = fmaxf(ix1, bj[0]), yy1 = fmaxf(iy1, bj[1]);
        float xx2 = fminf(ix2, bj[2]), yy2 = fminf(iy2, bj[3]);
        float iw = fmaxf(xx2 - xx1, 0.f), ih = fmaxf(yy2 - yy1, 0.f);
        float inter = iw * ih;
        float iou = inter / (ai + aj - inter + 1e-6f);
        pred = iou > 0.65f;
    }
    unsigned m = __ballot_sync(0xffffffffu, pred);
    if ((j & 31) == 0)
        g_mask[((size_t)(b * NMS_CAND + i)) * 32 + (j >> 5)] = m;
}

__global__ void nms_reduce_k() {
    extern __shared__ unsigned smask[];
    int b = blockIdx.x;
    for (int t = threadIdx.x; t < NMS_CAND * 32; t += 1024)
        smask[t] = g_mask[(size_t)b * NMS_CAND * 32 + t];
    __syncthreads();
    if (threadIdx.x < 32) {
        int lane = threadIdx.x;
        unsigned removed = 0u;
        for (int i = 0; i < NMS_CAND; i++) {
            unsigned rw = __shfl_sync(0xffffffffu, removed, i >> 5);
            if (!((rw >> (i & 31)) & 1u))
                removed |= smask[i * 32 + lane];
        }
        g_keep[b * 32 + lane] = ~removed;
    }
}

// ---------------- final select ----------------
__global__ void select_k(float* __restrict__ out) {
    __shared__ int ps[1024];
    __shared__ int s_total;
    int b = blockIdx.x;
    int tid = threadIdx.x;
    int kept = 0;
    if (tid < NMS_CAND)
        kept = (g_keep[b * 32 + (tid >> 5)] >> (tid & 31)) & 1;
    ps[tid] = kept;
    __syncthreads();
    for (int off = 1; off < 1024; off <<= 1) {
        int v = (tid >= off) ? ps[tid - off] : 0;
        __syncthreads();
        ps[tid] += v;
        __syncthreads();
    }
    if (tid == 1023) s_total = ps[1023];
    __syncthreads();
    int total = s_total;
    if (tid < NMS_CAND) {
        int excl = ps[tid] - kept;
        int pos = kept ? excl : total + (tid - excl);
        if (pos < MAX_DET) {
            int src = b * NMS_CAND + tid;
            out[(b * MAX_DET + pos) * 4 + 0] = g_cand_box[src * 4 + 0];
            out[(b * MAX_DET + pos) * 4 + 1] = g_cand_box[src * 4 + 1];
            out[(b * MAX_DET + pos) * 4 + 2] = g_cand_box[src * 4 + 2];
            out[(b * MAX_DET + pos) * 4 + 3] = g_cand_box[src * 4 + 3];
            out[BB * MAX_DET * 4 + b * MAX_DET + pos] = kept ? g_cand_sc[src] : 0.f;
            out[BB * MAX_DET * 5 + b * MAX_DET + pos] = (float)g_cand_lab[src];
        }
    }
}

// ---------------- launch ----------------
extern "C" void kernel_launch(void* const* d_in, const int* in_sizes, int n_in,
                              void* d_out, int out_size) {
    (void)in_sizes; (void)n_in; (void)out_size;
    const float* feat = (const float*)d_in[0];
    const float* cls_w_in  = (const float*)d_in[1];
    const float* cls_b_in  = (const float*)d_in[2];
    const float* cls_w_hid = (const float*)d_in[3];
    const float* cls_b_hid = (const float*)d_in[4];
    const float* cls_w_out = (const float*)d_in[5];
    const float* cls_b_out = (const float*)d_in[6];
    const float* obj_w_in  = (const float*)d_in[7];
    const float* obj_b_in  = (const float*)d_in[8];
    const float* obj_w_hid = (const float*)d_in[9];
    const float* obj_b_hid = (const float*)d_in[10];
    const float* obj_w_out = (const float*)d_in[11];
    const float* obj_b_out = (const float*)d_in[12];
    const float* box_w_in  = (const float*)d_in[13];
    const float* box_b_in  = (const float*)d_in[14];
    const float* box_w_hid = (const float*)d_in[15];
    const float* box_b_hid = (const float*)d_in[16];
    const float* box_w_out = (const float*)d_in[17];
    const float* box_b_out = (const float*)d_in[18];
    float* out = (float*)d_out;

    float *bA, *bB, *WT;
    cudaGetSymbolAddress((void**)&bA, g_bA);
    cudaGetSymbolAddress((void**)&bB, g_bB);
    cudaGetSymbolAddress((void**)&WT, g_WT);
    const size_t HS = (size_t)CC * MPIX;
    float* A[3] = {bA, bA + HS, bA + 2 * HS};
    float* Bt[3] = {bB, bB + HS, bB + 2 * HS};

    const int gemm_smem = 6 * STG * (int)sizeof(float);   // 101376 B (3 stages)
    const int outdec_smem = (3 * STG16 + 1712 + 128 * 97) * (int)sizeof(float);
    cudaFuncSetAttribute(gemm3_k, cudaFuncAttributeMaxDynamicSharedMemorySize, gemm_smem);
    cudaFuncSetAttribute(outdec_k, cudaFuncAttributeMaxDynamicSharedMemorySize, outdec_smem);
    cudaFuncSetAttribute(nms_reduce_k, cudaFuncAttributeMaxDynamicSharedMemorySize, 131072);

    // 0) transpose all 15 weight matrices (feat is read directly by layer 0)
    wtrans_k<<<dim3(8, 8, 15), dim3(32, 8)>>>(cls_w_in, obj_w_in, box_w_in,
                                              cls_w_hid, obj_w_hid, box_w_hid);

    auto wt_in  = [&](int h) { return WT + (size_t)h * 65536; };
    auto wt_hid = [&](int h, int i) { return WT + (size_t)(3 + h * 4 + i) * 65536; };

    // 1) input layers (read feat directly)
    dim3 gg(2, MPIX / 128, 3);
    gemm3_k<<<gg, 256, gemm_smem>>>(feat, feat, feat,
                                    wt_in(0), wt_in(1), wt_in(2),
                                    cls_b_in, obj_b_in, box_b_in,
                                    A[0], A[1], A[2], 1);
    // 2) hidden layers
    float* cur[3] = {A[0], A[1], A[2]};
    float* nxt[3] = {Bt[0], Bt[1], Bt[2]};
    for (int i = 0; i < 4; i++) {
        gemm3_k<<<gg, 256, gemm_smem>>>(cur[0], cur[1], cur[2],
                                        wt_hid(0, i), wt_hid(1, i), wt_hid(2, i),
                                        cls_b_hid + i * 256,
                                        obj_b_hid + i * 256,
                                        box_b_hid + i * 256,
                                        nxt[0], nxt[1], nxt[2], 0);
        for (int h = 0; h < 3; h++) { float* t = cur[h]; cur[h] = nxt[h]; nxt[h] = t; }
    }

    // 3) fused out-layers + decode
    outdec_k<<<MPIX / 128, 256, outdec_smem>>>(cur[0], cur[1], cur[2],
                                               cls_w_out, cls_b_out,
                                               obj_w_out, obj_b_out,
                                               box_w_out, box_b_out);

    // 4) exact per-batch top-1000
    topk_k<<<BB, 1024>>>();

    // 5) NMS
    nms_mask_k<<<dim3(NMS_CAND, BB), 1024>>>();
    nms_reduce_k<<<BB, 1024, NMS_CAND * 32 * (int)sizeof(unsigned)>>>();

    // 6) final top-100 select
    select_k<<<BB, 1024>>>(out);
}

// round 11
// speedup vs baseline: 1.4868x; 1.4868x over previous
#include <cuda_runtime.h>
#include <cstdint>
#include <cstddef>

// ---------------- problem constants ----------------
#define BB 2
#define CC 256
#define HH 128
#define WW 128
#define HW 16384
#define MPIX 32768
#define NCLS 80
#define NMS_CAND 1000
#define MAX_DET 100
#define KB 32
#define STG (KB * 132)     // floats per stage per array
#define NPANEL (256 / KB)  // 8
#define STG16 (16 * 132)

// ---------------- scratch ----------------
// activations kept TRANSPOSED: [256][MPIX]
__device__ float g_X0[(size_t)CC * MPIX];
__device__ float g_bA[3][(size_t)CC * MPIX];
__device__ float g_bB[3][(size_t)CC * MPIX];
__device__ float g_WT[9 * 256 * 256];   // [k][n]: slots 0..2 in-layers, 3..8 composed pairs
__device__ float g_BE[6][256];          // composed biases
__device__ float g_score[MPIX];
__device__ int   g_label[MPIX];
__device__ float g_boxes[(size_t)MPIX * 4];
__device__ float g_cand_sc[BB * NMS_CAND];
__device__ int   g_cand_lab[BB * NMS_CAND];
__device__ float g_cand_box[BB * NMS_CAND * 4];
__device__ unsigned g_mask[(size_t)BB * NMS_CAND * 32];
__device__ unsigned g_keep[BB * 32];

// ---------------- helpers ----------------
__device__ __forceinline__ unsigned smem_addr(const void* p) {
    return (unsigned)__cvta_generic_to_shared(p);
}
__device__ __forceinline__ void cpasync16(unsigned dst, const float* src) {
    asm volatile("cp.async.cg.shared.global [%0], [%1], 16;\n" :: "r"(dst), "l"(src));
}
__device__ __forceinline__ void cp_commit() {
    asm volatile("cp.async.commit_group;\n" ::: "memory");
}
template <int N>
__device__ __forceinline__ void cp_wait() {
    asm volatile("cp.async.wait_group %0;\n" :: "n"(N) : "memory");
}
__device__ __forceinline__ void ffma2(unsigned long long& d, unsigned long long a, unsigned long long b) {
    asm("fma.rn.f32x2 %0, %1, %2, %0;" : "+l"(d) : "l"(a), "l"(b));
}
__device__ __forceinline__ unsigned long long dup2(float x) {
    unsigned long long r;
    asm("mov.b64 %0, {%1, %1};" : "=l"(r) : "f"(x));
    return r;
}
__device__ __forceinline__ void unpack2(unsigned long long v, float& lo, float& hi) {
    asm("mov.b64 {%0, %1}, %2;" : "=f"(lo), "=f"(hi) : "l"(v));
}
__device__ __forceinline__ float sigmoidf_(float x) { return 1.f / (1.f + expf(-x)); }

// ---------------- feat (B,C,HW) -> X0T [C][B*HW] (pure strided copy) ----------------
__global__ void x0t_k(const float* __restrict__ feat) {
    int r = blockIdx.x;            // 0..511
    int c = r & 255, b = r >> 8;
    const float4* src = (const float4*)(feat + (size_t)(b * CC + c) * HW);
    float4* dst = (float4*)(g_X0 + (size_t)c * MPIX + b * HW);
    for (int i = threadIdx.x; i < HW / 4; i += 256) dst[i] = src[i];
}

// ---------------- weight transpose for the 3 in-layers: W[n][k] -> WT[k][n] ----------------
__global__ void wtrans_k(const float* __restrict__ cwin, const float* __restrict__ owin,
                         const float* __restrict__ bwin) {
    __shared__ float t[32][33];
    int z = blockIdx.z;   // 0..2
    const float* src = z == 0 ? cwin : (z == 1 ? owin : bwin);
    float* dst = g_WT + (size_t)z * 65536;
    int x0 = blockIdx.x * 32, y0 = blockIdx.y * 32;
    int tx = threadIdx.x, ty = threadIdx.y;   // (32,8)
    #pragma unroll
    for (int i = 0; i < 32; i += 8)
        t[ty + i][tx] = src[(size_t)(y0 + ty + i) * 256 + x0 + tx];
    __syncthreads();
    #pragma unroll
    for (int i = 0; i < 32; i += 8)
        dst[(size_t)(x0 + ty + i) * 256 + y0 + tx] = t[tx][ty + i];
}

// ---------------- compose pairs of residual layers ----------------
// For head h, pair p (layers 2p, 2p+1 of that head's hidden stack):
//   C = W1 + W2 + W2*W1   stored TRANSPOSED into WT slot (3 + h*2 + p): WT[k][n] = C[n][k]
__global__ void compose_k(const float* __restrict__ cwh, const float* __restrict__ owh,
                          const float* __restrict__ bwh) {
    extern __shared__ float cs[];
    float* sW2 = cs;           // [32][256]  W2 rows n0..n0+31
    float* sW1 = cs + 8192;    // [256][33]  W1 cols k0..k0+31
    int z = blockIdx.z, h = z >> 1, p = z & 1;
    const float* hw = h == 0 ? cwh : (h == 1 ? owh : bwh);
    const float* W1 = hw + (size_t)(2 * p) * 65536;
    const float* W2 = hw + (size_t)(2 * p + 1) * 65536;
    float* dst = g_WT + (size_t)(3 + z) * 65536;
    int n0 = blockIdx.x * 32, k0 = blockIdx.y * 32;
    int tid = threadIdx.x;     // 256

    for (int idx = tid; idx < 32 * 256; idx += 256) {
        int i = idx >> 8, j = idx & 255;
        sW2[i * 256 + j] = W2[(size_t)(n0 + i) * 256 + j];
    }
    for (int idx = tid; idx < 256 * 32; idx += 256) {
        int j = idx >> 5, b = idx & 31;
        sW1[j * 33 + b] = W1[(size_t)j * 256 + k0 + b];
    }
    __syncthreads();

    int a = tid >> 3;            // n offset 0..31
    int bg = (tid & 7) * 4;      // k offset group
    float acc[4] = {0.f, 0.f, 0.f, 0.f};
    for (int j = 0; j < 256; j++) {
        float v2 = sW2[a * 256 + j];
        acc[0] = fmaf(v2, sW1[j * 33 + bg + 0], acc[0]);
        acc[1] = fmaf(v2, sW1[j * 33 + bg + 1], acc[1]);
        acc[2] = fmaf(v2, sW1[j * 33 + bg + 2], acc[2]);
        acc[3] = fmaf(v2, sW1[j * 33 + bg + 3], acc[3]);
    }
    #pragma unroll
    for (int q = 0; q < 4; q++) {
        int k = k0 + bg + q, n = n0 + a;
        float w1nk = W1[(size_t)n * 256 + k];
        float w2nk = sW2[a * 256 + k];
        dst[(size_t)k * 256 + n] = w1nk + w2nk + acc[q];
    }
}

// composed bias: b_eff = b1 + W2*b1 + b2 (dataset biases are zero, but keep general)
__global__ void biascomp_k(const float* __restrict__ cwh, const float* __restrict__ owh,
                           const float* __restrict__ bwh, const float* __restrict__ cbh,
                           const float* __restrict__ obh, const float* __restrict__ bbh) {
    int z = blockIdx.x, h = z >> 1, p = z & 1;
    const float* hw = h == 0 ? cwh : (h == 1 ? owh : bwh);
    const float* hb = h == 0 ? cbh : (h == 1 ? obh : bbh);
    const float* W2 = hw + (size_t)(2 * p + 1) * 65536;
    const float* b1 = hb + (2 * p) * 256;
    const float* b2 = hb + (2 * p + 1) * 256;
    int n = threadIdx.x;
    float acc = b1[n] + b2[n];
    for (int j = 0; j < 256; j++)
        acc = fmaf(W2[(size_t)n * 256 + j], b1[j], acc);
    g_BE[z][n] = acc;
}

// ---------------- 3-head fp32 GEMM (R7 verbatim: transposed operands, 3-stage) ----------------
// A: [256][MPIX] k-major, W: [256][256] k-major.
// O[n][m] = sum_k A[k][m]*W[k][n] + bias[n] (+A[n][m] if residual)
__global__ void __launch_bounds__(256, 2) gemm3_k(
    const float* __restrict__ A0, const float* __restrict__ A1, const float* __restrict__ A2,
    const float* __restrict__ W0, const float* __restrict__ W1, const float* __restrict__ W2,
    const float* __restrict__ c0, const float* __restrict__ c1, const float* __restrict__ c2,
    float* __restrict__ O0, float* __restrict__ O1, float* __restrict__ O2,
    int residual)
{
    extern __shared__ __align__(16) float sm[];
    float* As = sm;              // [3][KB][132]
    float* Bs = sm + 3 * STG;    // [3][KB][132]

    const int head = blockIdx.z;
    const float* A    = head == 0 ? A0 : head == 1 ? A1 : A2;
    const float* Wt   = head == 0 ? W0 : head == 1 ? W1 : W2;
    const float* bias = head == 0 ? c0 : head == 1 ? c1 : c2;
    float* Cout       = head == 0 ? O0 : head == 1 ? O1 : O2;

    const int m0 = blockIdx.y * 128;
    const int n0 = blockIdx.x * 128;
    const int tid = threadIdx.x;
    const int tx = tid & 15, ty = tid >> 4;

    auto load_panel = [&](int p, int s) {
        float* Asd = As + s * STG;
        float* Bsd = Bs + s * STG;
        #pragma unroll
        for (int l = 0; l < 4; l++) {
            int idx = tid + l * 256;
            int k = idx >> 5, c4 = idx & 31;
            cpasync16(smem_addr(&Asd[k * 132 + c4 * 4]),
                      A + (size_t)(p * KB + k) * MPIX + m0 + c4 * 4);
        }
        #pragma unroll
        for (int l = 0; l < 4; l++) {
            int idx = tid + l * 256;
            int k = idx >> 5, c4 = idx & 31;
            cpasync16(smem_addr(&Bsd[k * 132 + c4 * 4]),
                      Wt + (size_t)(p * KB + k) * 256 + n0 + c4 * 4);
        }
        cp_commit();
    };

    unsigned long long acc2[8][4];   // [n-slot][m-pair]
    #pragma unroll
    for (int j = 0; j < 8; j++)
        #pragma unroll
        for (int q = 0; q < 4; q++) acc2[j][q] = 0ull;

    load_panel(0, 0);
    load_panel(1, 1);

    #pragma unroll 1
    for (int p = 0; p < NPANEL; p++) {
        if (p < NPANEL - 1) cp_wait<1>(); else cp_wait<0>();
        __syncthreads();
        if (p + 2 < NPANEL) load_panel(p + 2, (p + 2) % 3);
        const float* Asd = As + (p % 3) * STG;
        const float* Bsd = Bs + (p % 3) * STG;
        #pragma unroll 8
        for (int kk = 0; kk < KB; kk++) {
            ulonglong2 aA = *(const ulonglong2*)&Asd[kk * 132 + 4 * ty];
            ulonglong2 aB = *(const ulonglong2*)&Asd[kk * 132 + 64 + 4 * ty];
            float4 bb0 = *(const float4*)&Bsd[kk * 132 + 4 * tx];
            float4 bb1 = *(const float4*)&Bsd[kk * 132 + 64 + 4 * tx];
            unsigned long long am[4] = {aA.x, aA.y, aB.x, aB.y};
            unsigned long long bd[8] = {dup2(bb0.x), dup2(bb0.y), dup2(bb0.z), dup2(bb0.w),
                                        dup2(bb1.x), dup2(bb1.y), dup2(bb1.z), dup2(bb1.w)};
            #pragma unroll
            for (int j = 0; j < 8; j++)
                #pragma unroll
                for (int q = 0; q < 4; q++)
                    ffma2(acc2[j][q], am[q], bd[j]);
        }
    }

    #pragma unroll
    for (int j = 0; j < 8; j++) {
        int n = n0 + ((j < 4) ? (4 * tx + j) : (64 + 4 * tx + (j - 4)));
        float bv = bias[n];
        float f0, f1, f2, f3, h0, h1, h2, h3;
        unpack2(acc2[j][0], f0, f1);
        unpack2(acc2[j][1], f2, f3);
        unpack2(acc2[j][2], h0, h1);
        unpack2(acc2[j][3], h2, h3);
        float4 v0 = make_float4(f0 + bv, f1 + bv, f2 + bv, f3 + bv);
        float4 v1 = make_float4(h0 + bv, h1 + bv, h2 + bv, h3 + bv);
        if (residual) {
            float4 r0 = *(const float4*)(A + (size_t)n * MPIX + m0 + 4 * ty);
            float4 r1 = *(const float4*)(A + (size_t)n * MPIX + m0 + 64 + 4 * ty);
            v0.x += r0.x; v0.y += r0.y; v0.z += r0.z; v0.w += r0.w;
            v1.x += r1.x; v1.y += r1.y; v1.z += r1.z; v1.w += r1.w;
        }
        *(float4*)(Cout + (size_t)n * MPIX + m0 + 4 * ty) = v0;
        *(float4*)(Cout + (size_t)n * MPIX + m0 + 64 + 4 * ty) = v1;
    }
}

// ---------------- fused out-layers + decode ----------------
__global__ void __launch_bounds__(256) outdec_k(
    const float* __restrict__ Acls, const float* __restrict__ Aobj, const float* __restrict__ Abox,
    const float* __restrict__ cw, const float* __restrict__ cb,
    const float* __restrict__ ow, const float* __restrict__ ob,
    const float* __restrict__ bw, const float* __restrict__ bbx)
{
    extern __shared__ __align__(16) float sm[];
    float* As_c = sm;
    float* As_b = sm + STG16;
    float* As_o = sm + 2 * STG16;
    float* Bsw  = sm + 3 * STG16;
    float* sbias = sm + 3 * STG16 + 1600;
    float* slog = sm + 3 * STG16 + 1712;

    const int m0 = blockIdx.x * 128;
    const int tid = threadIdx.x;
    const int tx = tid & 15, ty = tid >> 4;

    if (tid < 96) {
        float bv = 0.f;
        if (tid < 80) bv = cb[tid];
        else if (tid < 84) bv = bbx[tid - 80];
        else if (tid == 84) bv = ob[0];
        sbias[tid] = bv;
    }

    float acc[8][6];
    #pragma unroll
    for (int i = 0; i < 8; i++)
        #pragma unroll
        for (int j = 0; j < 6; j++) acc[i][j] = 0.f;

    #pragma unroll 1
    for (int p = 0; p < 16; p++) {
        __syncthreads();
        #pragma unroll
        for (int lq = 0; lq < 2; lq++) {
            int idx = tid + lq * 256;
            int k = idx >> 5, c4 = idx & 31;
            size_t off = (size_t)(p * 16 + k) * MPIX + m0 + c4 * 4;
            *(float4*)&As_c[k * 132 + c4 * 4] = *(const float4*)(Acls + off);
            *(float4*)&As_b[k * 132 + c4 * 4] = *(const float4*)(Abox + off);
            *(float4*)&As_o[k * 132 + c4 * 4] = *(const float4*)(Aobj + off);
        }
        #pragma unroll
        for (int lq = 0; lq < 6; lq++) {
            int idx = tid + lq * 256;
            int k = idx & 15, slot = idx >> 4;
            float v = 0.f;
            if (slot < 80)       v = cw[slot * 256 + p * 16 + k];
            else if (slot < 84)  v = bw[(slot - 80) * 256 + p * 16 + k];
            else if (slot == 84) v = ow[p * 16 + k];
            Bsw[k * 100 + slot] = v;
        }
        __syncthreads();

        const float* As_x = (tx < 4) ? As_b : (tx == 4 ? As_o : As_c);
        #pragma unroll
        for (int kk = 0; kk < 16; kk++) {
            float4 a0 = *(const float4*)&As_c[kk * 132 + ty * 8];
            float4 a1 = *(const float4*)&As_c[kk * 132 + ty * 8 + 4];
            float4 x0 = *(const float4*)&As_x[kk * 132 + ty * 8];
            float4 x1 = *(const float4*)&As_x[kk * 132 + ty * 8 + 4];
            float ac[8] = {a0.x, a0.y, a0.z, a0.w, a1.x, a1.y, a1.z, a1.w};
            float ax[8] = {x0.x, x0.y, x0.z, x0.w, x1.x, x1.y, x1.z, x1.w};
            float b[6];
            #pragma unroll
            for (int j = 0; j < 6; j++) b[j] = Bsw[kk * 100 + tx + 16 * j];
            #pragma unroll
            for (int i = 0; i < 8; i++) {
                #pragma unroll
                for (int j = 0; j < 5; j++)
                    acc[i][j] = fmaf(ac[i], b[j], acc[i][j]);
                acc[i][5] = fmaf(ax[i], b[5], acc[i][5]);
            }
        }
    }

    __syncthreads();
    #pragma unroll
    for (int i = 0; i < 8; i++)
        #pragma unroll
        for (int j = 0; j < 6; j++) {
            int col = tx + 16 * j;
            slog[(ty * 8 + i) * 97 + col] = acc[i][j] + sbias[col];
        }
    __syncthreads();

    if (tid < 128) {
        const float* lg = &slog[tid * 97];
        float objp = sigmoidf_(lg[84]);
        float best = -1.f; int bl = 0;
        #pragma unroll 4
        for (int c = 0; c < NCLS; c++) {
            float pr = sigmoidf_(lg[c]) * objp;
            if (pr > best) { best = pr; bl = c; }
        }
        int n = m0 + tid;
        g_score[n] = best;
        g_label[n] = bl;
        int hw = n & (HW - 1);
        int h = hw >> 7, w = hw & 127;
        float px = (w + 0.5f) * 8.f;
        float py = (h + 0.5f) * 8.f;
        float l = expf(lg[80]) * 8.f;
        float t = expf(lg[81]) * 8.f;
        float r = expf(lg[82]) * 8.f;
        float d = expf(lg[83]) * 8.f;
        g_boxes[(size_t)n * 4 + 0] = px - l;
        g_boxes[(size_t)n * 4 + 1] = py - t;
        g_boxes[(size_t)n * 4 + 2] = px + r;
        g_boxes[(size_t)n * 4 + 3] = py + d;
    }
}

// ---------------- exact top-1000: warp-aggregated histograms + compact + bitonic ----------------
__global__ void topk_k() {
    __shared__ int hist[256];
    __shared__ int s_b1, s_n1, s_thr, s_cnt;
    __shared__ unsigned long long skey[4096];
    int b = blockIdx.x;
    int tid = threadIdx.x;   // 1024
    int lane = tid & 31;

    if (tid < 256) hist[tid] = 0;
    __syncthreads();
    for (int i = tid; i < HW; i += 1024) {
        unsigned u = __float_as_uint(g_score[b * HW + i]);
        int bin = u >> 24;
        unsigned mm = __match_any_sync(0xffffffffu, bin);
        if (lane == (__ffs(mm) - 1)) atomicAdd(&hist[bin], __popc(mm));
    }
    __syncthreads();
    if (tid == 0) {
        int acc = 0; int bin = 255;
        for (; bin > 0; bin--) { if (acc + hist[bin] >= NMS_CAND) break; acc += hist[bin]; }
        s_b1 = bin; s_n1 = acc;
    }
    __syncthreads();
    int b1 = s_b1, n1 = s_n1;
    if (tid < 256) hist[tid] = 0;
    __syncthreads();
    for (int i = tid; i < HW; i += 1024) {
        unsigned u = __float_as_uint(g_score[b * HW + i]);
        bool sel = ((int)(u >> 24) == b1);
        unsigned active = __ballot_sync(0xffffffffu, sel);
        if (sel) {
            int bin2 = (u >> 16) & 255;
            unsigned mm = __match_any_sync(active, bin2);
            if (lane == (__ffs(mm) - 1)) atomicAdd(&hist[bin2], __popc(mm));
        }
    }
    __syncthreads();
    if (tid == 0) {
        int acc = n1; int bin = 255;
        for (; bin > 0; bin--) { if (acc + hist[bin] >= NMS_CAND) break; acc += hist[bin]; }
        s_thr = (b1 << 8) | bin;
        s_cnt = 0;
    }
    __syncthreads();
    unsigned thr = (unsigned)s_thr;
    for (int i = tid; i < HW; i += 1024) {
        unsigned u = __float_as_uint(g_score[b * HW + i]);
        bool pass = (u >> 16) >= thr;
        unsigned bal = __ballot_sync(0xffffffffu, pass);
        int base = 0;
        if (lane == 0 && bal) base = atomicAdd(&s_cnt, __popc(bal));
        base = __shfl_sync(0xffffffffu, base, 0);
        if (pass) {
            int pos = base + __popc(bal & ((1u << lane) - 1u));
            if (pos < 4096)
                skey[pos] = ((unsigned long long)(~u) << 32) | (unsigned)i;
        }
    }
    __syncthreads();
    int cnt = s_cnt < 4096 ? s_cnt : 4096;
    for (int i = tid; i < 4096; i += 1024)
        if (i >= cnt) skey[i] = 0xFFFFFFFFFFFFFFFFull;
    __syncthreads();

    for (int k = 2; k <= 4096; k <<= 1) {
        for (int j = k >> 1; j > 0; j >>= 1) {
            #pragma unroll
            for (int l = 0; l < 4; l++) {
                int i = tid + l * 1024;
                int ixj = i ^ j;
                if (ixj > i) {
                    bool up = ((i & k) == 0);
                    unsigned long long a = skey[i], c = skey[ixj];
                    if (up ? (a > c) : (a < c)) { skey[i] = c; skey[ixj] = a; }
                }
            }
            __syncthreads();
        }
    }

    if (tid < NMS_CAND) {
        unsigned long long key = skey[tid];
        int idx = (int)(unsigned)key;
        float s = __uint_as_float(~(unsigned)(key >> 32));
        int g = b * HW + idx;
        int dst = b * NMS_CAND + tid;
        g_cand_sc[dst] = s;
        g_cand_lab[dst] = g_label[g];
        #pragma unroll
        for (int q = 0; q < 4; q++)
            g_cand_box[dst * 4 + q] = g_boxes[(size_t)g * 4 + q];
    }
}

// ---------------- NMS ----------------
__global__ void nms_mask_k() {
    int i = blockIdx.x;
    int b = blockIdx.y;
    int j = threadIdx.x;
    const float* bi = &g_cand_box[(b * NMS_CAND + i) * 4];
    float ix1 = bi[0], iy1 = bi[1], ix2 = bi[2], iy2 = bi[3];
    float ai = fmaxf(ix2 - ix1, 0.f) * fmaxf(iy2 - iy1, 0.f);
    bool pred = false;
    if (j < NMS_CAND && j > i) {
        const float* bj = &g_cand_box[(b * NMS_CAND + j) * 4];
        float aj = fmaxf(bj[2] - bj[0], 0.f) * fmaxf(bj[3] - bj[1], 0.f);
        float xx1 = fmaxf(ix1, bj[0]), yy1 = fmaxf(iy1, bj[1]);
        float xx2 = fminf(ix2, bj[2]), yy2 = fminf(iy2, bj[3]);
        float iw = fmaxf(xx2 - xx1, 0.f), ih = fmaxf(yy2 - yy1, 0.f);
        float inter = iw * ih;
        float iou = inter / (ai + aj - inter + 1e-6f);
        pred = iou > 0.65f;
    }
    unsigned m = __ballot_sync(0xffffffffu, pred);
    if ((j & 31) == 0)
        g_mask[((size_t)(b * NMS_CAND + i)) * 32 + (j >> 5)] = m;
}

__global__ void nms_reduce_k() {
    extern __shared__ unsigned smask[];
    int b = blockIdx.x;
    for (int t = threadIdx.x; t < NMS_CAND * 32; t += 1024)
        smask[t] = g_mask[(size_t)b * NMS_CAND * 32 + t];
    __syncthreads();
    if (threadIdx.x < 32) {
        int lane = threadIdx.x;
        unsigned removed = 0u;
        for (int i = 0; i < NMS_CAND; i++) {
            unsigned rw = __shfl_sync(0xffffffffu, removed, i >> 5);
            if (!((rw >> (i & 31)) & 1u))
                removed |= smask[i * 32 + lane];
        }
        g_keep[b * 32 + lane] = ~removed;
    }
}

// ---------------- final select ----------------
__global__ void select_k(float* __restrict__ out) {
    __shared__ int ps[1024];
    __shared__ int s_total;
    int b = blockIdx.x;
    int tid = threadIdx.x;
    int kept = 0;
    if (tid < NMS_CAND)
        kept = (g_keep[b * 32 + (tid >> 5)] >> (tid & 31)) & 1;
    ps[tid] = kept;
    __syncthreads();
    for (int off = 1; off < 1024; off <<= 1) {
        int v = (tid >= off) ? ps[tid - off] : 0;
        __syncthreads();
        ps[tid] += v;
        __syncthreads();
    }
    if (tid == 1023) s_total = ps[1023];
    __syncthreads();
    int total = s_total;
    if (tid < NMS_CAND) {
        int excl = ps[tid] - kept;
        int pos = kept ? excl : total + (tid - excl);
        if (pos < MAX_DET) {
            int src = b * NMS_CAND + tid;
            out[(b * MAX_DET + pos) * 4 + 0] = g_cand_box[src * 4 + 0];
            out[(b * MAX_DET + pos) * 4 + 1] = g_cand_box[src * 4 + 1];
            out[(b * MAX_DET + pos) * 4 + 2] = g_cand_box[src * 4 + 2];
            out[(b * MAX_DET + pos) * 4 + 3] = g_cand_box[src * 4 + 3];
            out[BB * MAX_DET * 4 + b * MAX_DET + pos] = kept ? g_cand_sc[src] : 0.f;
            out[BB * MAX_DET * 5 + b * MAX_DET + pos] = (float)g_cand_lab[src];
        }
    }
}

// ---------------- launch ----------------
extern "C" void kernel_launch(void* const* d_in, const int* in_sizes, int n_in,
                              void* d_out, int out_size) {
    (void)in_sizes; (void)n_in; (void)out_size;
    const float* feat = (const float*)d_in[0];
    const float* cls_w_in  = (const float*)d_in[1];
    const float* cls_b_in  = (const float*)d_in[2];
    const float* cls_w_hid = (const float*)d_in[3];
    const float* cls_b_hid = (const float*)d_in[4];
    const float* cls_w_out = (const float*)d_in[5];
    const float* cls_b_out = (const float*)d_in[6];
    const float* obj_w_in  = (const float*)d_in[7];
    const float* obj_b_in  = (const float*)d_in[8];
    const float* obj_w_hid = (const float*)d_in[9];
    const float* obj_b_hid = (const float*)d_in[10];
    const float* obj_w_out = (const float*)d_in[11];
    const float* obj_b_out = (const float*)d_in[12];
    const float* box_w_in  = (const float*)d_in[13];
    const float* box_b_in  = (const float*)d_in[14];
    const float* box_w_hid = (const float*)d_in[15];
    const float* box_b_hid = (const float*)d_in[16];
    const float* box_w_out = (const float*)d_in[17];
    const float* box_b_out = (const float*)d_in[18];
    float* out = (float*)d_out;

    float *X0, *bA, *bB, *WT, *BE;
    cudaGetSymbolAddress((void**)&X0, g_X0);
    cudaGetSymbolAddress((void**)&bA, g_bA);
    cudaGetSymbolAddress((void**)&bB, g_bB);
    cudaGetSymbolAddress((void**)&WT, g_WT);
    cudaGetSymbolAddress((void**)&BE, g_BE);
    const size_t HS = (size_t)CC * MPIX;
    float* A[3] = {bA, bA + HS, bA + 2 * HS};
    float* Bt[3] = {bB, bB + HS, bB + 2 * HS};

    const int gemm_smem = 6 * STG * (int)sizeof(float);   // 101376 B
    const int outdec_smem = (3 * STG16 + 1712 + 128 * 97) * (int)sizeof(float);
    const int comp_smem = (8192 + 256 * 33) * (int)sizeof(float);   // 66560 B
    cudaFuncSetAttribute(gemm3_k, cudaFuncAttributeMaxDynamicSharedMemorySize, gemm_smem);
    cudaFuncSetAttribute(outdec_k, cudaFuncAttributeMaxDynamicSharedMemorySize, outdec_smem);
    cudaFuncSetAttribute(compose_k, cudaFuncAttributeMaxDynamicSharedMemorySize, comp_smem);
    cudaFuncSetAttribute(nms_reduce_k, cudaFuncAttributeMaxDynamicSharedMemorySize, 131072);

    // 0) prologue: pack feat + transpose in-layer weights + compose hidden pairs
    x0t_k<<<512, 256>>>(feat);
    wtrans_k<<<dim3(8, 8, 3), dim3(32, 8)>>>(cls_w_in, obj_w_in, box_w_in);
    compose_k<<<dim3(8, 8, 6), 256, comp_smem>>>(cls_w_hid, obj_w_hid, box_w_hid);
    biascomp_k<<<6, 256>>>(cls_w_hid, obj_w_hid, box_w_hid,
                           cls_b_hid, obj_b_hid, box_b_hid);

    auto wt_in   = [&](int h) { return WT + (size_t)h * 65536; };
    auto wt_comp = [&](int h, int p) { return WT + (size_t)(3 + h * 2 + p) * 65536; };
    auto be      = [&](int h, int p) { return BE + (h * 2 + p) * 256; };

    // 1) input layers
    dim3 gg(2, MPIX / 128, 3);
    gemm3_k<<<gg, 256, gemm_smem>>>(X0, X0, X0,
                                    wt_in(0), wt_in(1), wt_in(2),
                                    cls_b_in, obj_b_in, box_b_in,
                                    A[0], A[1], A[2], 0);
    // 2) composed residual pair 1 (hidden layers 0+1)
    gemm3_k<<<gg, 256, gemm_smem>>>(A[0], A[1], A[2],
                                    wt_comp(0, 0), wt_comp(1, 0), wt_comp(2, 0),
                                    be(0, 0), be(1, 0), be(2, 0),
                                    Bt[0], Bt[1], Bt[2], 1);
    // 3) composed residual pair 2 (hidden layers 2+3)
    gemm3_k<<<gg, 256, gemm_smem>>>(Bt[0], Bt[1], Bt[2],
                                    wt_comp(0, 1), wt_comp(1, 1), wt_comp(2, 1),
                                    be(0, 1), be(1, 1), be(2, 1),
                                    A[0], A[1], A[2], 1);

    // 4) fused out-layers + decode
    outdec_k<<<MPIX / 128, 256, outdec_smem>>>(A[0], A[1], A[2],
                                               cls_w_out, cls_b_out,
                                               obj_w_out, obj_b_out,
                                               box_w_out, box_b_out);

    // 5) exact per-batch top-1000
    topk_k<<<BB, 1024>>>();

    // 6) NMS
    nms_mask_k<<<dim3(NMS_CAND, BB), 1024>>>();
    nms_reduce_k<<<BB, 1024, NMS_CAND * 32 * (int)sizeof(unsigned)>>>();

    // 7) final top-100 select
    select_k<<<BB, 1024>>>(out);
}

// round 13
// speedup vs baseline: 5.4897x; 3.6923x over previous
#include <cuda_runtime.h>
#include <cstdint>
#include <cstddef>

// ---------------- problem constants ----------------
#define BB 2
#define CC 256
#define HW 16384
#define MPIX 32768
#define NCLS 80
#define NMS_CAND 1000
#define MAX_DET 100
#define STG16 (16 * 132)

// ---------------- scratch ----------------
__device__ float g_P[6 * 65536];     // pair compositions P = W1 + W2 + W2*W1 (row-major [n][k])
__device__ float g_M[3 * 65536];     // M = P1 + P2 + P2*P1 per head
__device__ float g_G[3 * 65536];     // G = (I+M)*W_in per head
__device__ float g_WF[96 * 256];     // full row-major weights: 0..79 cls, 80..83 box, 84 obj, 85..95 zero
__device__ float g_bP[6 * 256];
__device__ float g_bM[3 * 256];
__device__ float g_b5[3 * 256];
__device__ float g_bF[96];
__device__ float g_score[MPIX];
__device__ int   g_label[MPIX];
__device__ float g_boxes[(size_t)MPIX * 4];
__device__ float g_cand_sc[BB * NMS_CAND];
__device__ int   g_cand_lab[BB * NMS_CAND];
__device__ float g_cand_box[BB * NMS_CAND * 4];
__device__ unsigned g_mask[(size_t)BB * NMS_CAND * 32];
__device__ unsigned g_keep[BB * 32];

__device__ __forceinline__ float sigmoidf_(float x) { return 1.f / (1.f + expf(-x)); }

// ---------------- generic 256x256 composition: dst = A + addB*B + B*A ----------------
// mode 0 (z=0..5): A=W1, B=W2 of hidden pair        -> g_P[z]
// mode 1 (z=0..2): A=P1, B=P2                       -> g_M[z]
// mode 2 (z=0..2): A=W_in, B=M, addB=0              -> g_G[z]   (G = W_in + M*W_in)
__global__ void comp_k(int mode,
                       const float* __restrict__ cwh, const float* __restrict__ owh,
                       const float* __restrict__ bwh,
                       const float* __restrict__ cwin, const float* __restrict__ owin,
                       const float* __restrict__ bwin) {
    extern __shared__ float cs[];
    float* sB = cs;            // [32][256]
    float* sA = cs + 8192;     // [256][33]
    int z = blockIdx.z;
    const float *A, *B;
    float* dst;
    int addB = 1;
    if (mode == 0) {
        int h = z >> 1, p = z & 1;
        const float* hw = h == 0 ? cwh : (h == 1 ? owh : bwh);
        A = hw + (size_t)(2 * p) * 65536;
        B = hw + (size_t)(2 * p + 1) * 65536;
        dst = g_P + (size_t)z * 65536;
    } else if (mode == 1) {
        A = g_P + (size_t)(2 * z) * 65536;
        B = g_P + (size_t)(2 * z + 1) * 65536;
        dst = g_M + (size_t)z * 65536;
    } else {
        A = z == 0 ? cwin : (z == 1 ? owin : bwin);
        B = g_M + (size_t)z * 65536;
        dst = g_G + (size_t)z * 65536;
        addB = 0;
    }
    int n0 = blockIdx.x * 32, k0 = blockIdx.y * 32;
    int tid = threadIdx.x;   // 256

    for (int idx = tid; idx < 32 * 256; idx += 256) {
        int i = idx >> 8, j = idx & 255;
        sB[i * 256 + j] = B[(size_t)(n0 + i) * 256 + j];
    }
    for (int idx = tid; idx < 256 * 32; idx += 256) {
        int j = idx >> 5, b = idx & 31;
        sA[j * 33 + b] = A[(size_t)j * 256 + k0 + b];
    }
    __syncthreads();

    int a = tid >> 3;
    int bg = (tid & 7) * 4;
    float acc[4] = {0.f, 0.f, 0.f, 0.f};
    for (int j = 0; j < 256; j++) {
        float v2 = sB[a * 256 + j];
        acc[0] = fmaf(v2, sA[j * 33 + bg + 0], acc[0]);
        acc[1] = fmaf(v2, sA[j * 33 + bg + 1], acc[1]);
        acc[2] = fmaf(v2, sA[j * 33 + bg + 2], acc[2]);
        acc[3] = fmaf(v2, sA[j * 33 + bg + 3], acc[3]);
    }
    #pragma unroll
    for (int q = 0; q < 4; q++) {
        int n = n0 + a, k = k0 + bg + q;
        float v = sA[n * 33 + bg + q] + acc[q];
        if (addB) v += sB[a * 256 + k];
        dst[(size_t)n * 256 + k] = v;
    }
}

// ---------------- generic bias composition: dst = a + B*a + c (warp per row) ----------------
// stage 0 (z=0..5): a=b1, B=W2, c=b2        -> g_bP
// stage 1 (z=0..2): a=bP1, B=P2, c=bP2      -> g_bM
// stage 2 (z=0..2): a=b_in, B=M, c=bM       -> g_b5
__global__ void biasv_k(int stage,
                        const float* __restrict__ cwh, const float* __restrict__ owh,
                        const float* __restrict__ bwh,
                        const float* __restrict__ cbh, const float* __restrict__ obh,
                        const float* __restrict__ bbh,
                        const float* __restrict__ cbin, const float* __restrict__ obin,
                        const float* __restrict__ bbin) {
    int z = blockIdx.x;
    const float *a, *B, *c;
    float* dst;
    if (stage == 0) {
        int h = z >> 1, p = z & 1;
        const float* hw = h == 0 ? cwh : (h == 1 ? owh : bwh);
        const float* hb = h == 0 ? cbh : (h == 1 ? obh : bbh);
        a = hb + (2 * p) * 256;
        B = hw + (size_t)(2 * p + 1) * 65536;
        c = hb + (2 * p + 1) * 256;
        dst = g_bP + z * 256;
    } else if (stage == 1) {
        a = g_bP + (2 * z) * 256;
        B = g_P + (size_t)(2 * z + 1) * 65536;
        c = g_bP + (2 * z + 1) * 256;
        dst = g_bM + z * 256;
    } else {
        a = z == 0 ? cbin : (z == 1 ? obin : bbin);
        B = g_M + (size_t)z * 65536;
        c = g_bM + z * 256;
        dst = g_b5 + z * 256;
    }
    __shared__ float sa[256];
    int tid = threadIdx.x, lane = tid & 31, warp = tid >> 5;
    sa[tid] = a[tid];
    __syncthreads();
    for (int r = 0; r < 32; r++) {
        int n = r * 8 + warp;
        float s = 0.f;
        #pragma unroll
        for (int q = 0; q < 8; q++)
            s = fmaf(B[(size_t)n * 256 + q * 32 + lane], sa[q * 32 + lane], s);
        #pragma unroll
        for (int off = 16; off > 0; off >>= 1)
            s += __shfl_xor_sync(0xffffffffu, s, off);
        if (lane == 0) dst[n] = sa[n] + s + c[n];
    }
}

// ---------------- final weight/bias rows: WF[s][k] = wout_row . G, bF[s] = wout_row . b5 + bout ----------------
__global__ void wf_k(const float* __restrict__ cwo, const float* __restrict__ cbo,
                     const float* __restrict__ owo, const float* __restrict__ obo,
                     const float* __restrict__ bwo, const float* __restrict__ bbo) {
    int s = blockIdx.x;   // 0..95
    int t = threadIdx.x;  // 256
    __shared__ float sw[256];
    __shared__ float red[256];
    const float* wrow = nullptr;
    const float* G = nullptr;
    const float* b5 = nullptr;
    float bout = 0.f;
    if (s < 80)      { wrow = cwo + (size_t)s * 256; G = g_G; b5 = g_b5; bout = cbo[s]; }
    else if (s < 84) { wrow = bwo + (size_t)(s - 80) * 256; G = g_G + 2 * 65536; b5 = g_b5 + 2 * 256; bout = bbo[s - 80]; }
    else if (s == 84){ wrow = owo; G = g_G + 65536; b5 = g_b5 + 256; bout = obo[0]; }
    if (!wrow) {
        g_WF[(size_t)s * 256 + t] = 0.f;
        if (t == 0) g_bF[s] = 0.f;
        return;
    }
    sw[t] = wrow[t];
    __syncthreads();
    float acc = 0.f;
    for (int j = 0; j < 256; j++)
        acc = fmaf(sw[j], G[(size_t)j * 256 + t], acc);
    g_WF[(size_t)s * 256 + t] = acc;
    red[t] = sw[t] * b5[t];
    __syncthreads();
    for (int off = 128; off > 0; off >>= 1) {
        if (t < off) red[t] += red[t + off];
        __syncthreads();
    }
    if (t == 0) g_bF[s] = red[0] + bout;
}

// ---------------- fused full-network GEMM + decode ----------------
// logits[s][m] = sum_k WF[s][k]*feat[b][k][m] + bF[s];  then score/label/box decode.
__global__ void __launch_bounds__(256) fdec_k(const float* __restrict__ feat) {
    extern __shared__ __align__(16) float sm[];
    float* As   = sm;                    // [16][132]
    float* Bsw  = sm + STG16;            // [16][100]
    float* sbias = sm + STG16 + 1600;    // 112
    float* slog = sm + STG16 + 1712;     // [128][97]

    const int m0 = blockIdx.x * 128;
    const int b = m0 >> 14;
    const int mm = m0 & (HW - 1);
    const int tid = threadIdx.x;
    const int tx = tid & 15, ty = tid >> 4;

    if (tid < 96) sbias[tid] = g_bF[tid];

    float acc[8][6];
    #pragma unroll
    for (int i = 0; i < 8; i++)
        #pragma unroll
        for (int j = 0; j < 6; j++) acc[i][j] = 0.f;

    #pragma unroll 1
    for (int p = 0; p < 16; p++) {
        __syncthreads();
        #pragma unroll
        for (int lq = 0; lq < 2; lq++) {
            int idx = tid + lq * 256;
            int k = idx >> 5, c4 = idx & 31;
            *(float4*)&As[k * 132 + c4 * 4] =
                *(const float4*)(feat + ((size_t)(b * CC + p * 16 + k)) * HW + mm + c4 * 4);
        }
        #pragma unroll
        for (int lq = 0; lq < 6; lq++) {
            int idx = tid + lq * 256;
            int k = idx & 15, slot = idx >> 4;
            Bsw[k * 100 + slot] = g_WF[(size_t)slot * 256 + p * 16 + k];
        }
        __syncthreads();

        #pragma unroll
        for (int kk = 0; kk < 16; kk++) {
            float4 a0 = *(const float4*)&As[kk * 132 + ty * 8];
            float4 a1 = *(const float4*)&As[kk * 132 + ty * 8 + 4];
            float a[8] = {a0.x, a0.y, a0.z, a0.w, a1.x, a1.y, a1.z, a1.w};
            float bv[6];
            #pragma unroll
            for (int j = 0; j < 6; j++) bv[j] = Bsw[kk * 100 + tx + 16 * j];
            #pragma unroll
            for (int i = 0; i < 8; i++)
                #pragma unroll
                for (int j = 0; j < 6; j++)
                    acc[i][j] = fmaf(a[i], bv[j], acc[i][j]);
        }
    }

    __syncthreads();
    #pragma unroll
    for (int i = 0; i < 8; i++)
        #pragma unroll
        for (int j = 0; j < 6; j++) {
            int col = tx + 16 * j;
            slog[(ty * 8 + i) * 97 + col] = acc[i][j] + sbias[col];
        }
    __syncthreads();

    if (tid < 128) {
        const float* lg = &slog[tid * 97];
        float objp = sigmoidf_(lg[84]);
        float best = -1.f; int bl = 0;
        #pragma unroll 4
        for (int c = 0; c < NCLS; c++) {
            float pr = sigmoidf_(lg[c]) * objp;
            if (pr > best) { best = pr; bl = c; }
        }
        int n = m0 + tid;
        g_score[n] = best;
        g_label[n] = bl;
        int hw = n & (HW - 1);
        int h = hw >> 7, w = hw & 127;
        float px = (w + 0.5f) * 8.f;
        float py = (h + 0.5f) * 8.f;
        float l = expf(lg[80]) * 8.f;
        float t = expf(lg[81]) * 8.f;
        float r = expf(lg[82]) * 8.f;
        float d = expf(lg[83]) * 8.f;
        g_boxes[(size_t)n * 4 + 0] = px - l;
        g_boxes[(size_t)n * 4 + 1] = py - t;
        g_boxes[(size_t)n * 4 + 2] = px + r;
        g_boxes[(size_t)n * 4 + 3] = py + d;
    }
}

// ---------------- exact top-1000: warp-aggregated histograms + compact + bitonic ----------------
__global__ void topk_k() {
    __shared__ int hist[256];
    __shared__ int s_b1, s_n1, s_thr, s_cnt;
    __shared__ unsigned long long skey[4096];
    int b = blockIdx.x;
    int tid = threadIdx.x;   // 1024
    int lane = tid & 31;

    if (tid < 256) hist[tid] = 0;
    __syncthreads();
    for (int i = tid; i < HW; i += 1024) {
        unsigned u = __float_as_uint(g_score[b * HW + i]);
        int bin = u >> 24;
        unsigned mm = __match_any_sync(0xffffffffu, bin);
        if (lane == (__ffs(mm) - 1)) atomicAdd(&hist[bin], __popc(mm));
    }
    __syncthreads();
    if (tid == 0) {
        int acc = 0; int bin = 255;
        for (; bin > 0; bin--) { if (acc + hist[bin] >= NMS_CAND) break; acc += hist[bin]; }
        s_b1 = bin; s_n1 = acc;
    }
    __syncthreads();
    int b1 = s_b1, n1 = s_n1;
    if (tid < 256) hist[tid] = 0;
    __syncthreads();
    for (int i = tid; i < HW; i += 1024) {
        unsigned u = __float_as_uint(g_score[b * HW + i]);
        bool sel = ((int)(u >> 24) == b1);
        unsigned active = __ballot_sync(0xffffffffu, sel);
        if (sel) {
            int bin2 = (u >> 16) & 255;
            unsigned mm = __match_any_sync(active, bin2);
            if (lane == (__ffs(mm) - 1)) atomicAdd(&hist[bin2], __popc(mm));
        }
    }
    __syncthreads();
    if (tid == 0) {
        int acc = n1; int bin = 255;
        for (; bin > 0; bin--) { if (acc + hist[bin] >= NMS_CAND) break; acc += hist[bin]; }
        s_thr = (b1 << 8) | bin;
        s_cnt = 0;
    }
    __syncthreads();
    unsigned thr = (unsigned)s_thr;
    for (int i = tid; i < HW; i += 1024) {
        unsigned u = __float_as_uint(g_score[b * HW + i]);
        bool pass = (u >> 16) >= thr;
        unsigned bal = __ballot_sync(0xffffffffu, pass);
        int base = 0;
        if (lane == 0 && bal) base = atomicAdd(&s_cnt, __popc(bal));
        base = __shfl_sync(0xffffffffu, base, 0);
        if (pass) {
            int pos = base + __popc(bal & ((1u << lane) - 1u));
            if (pos < 4096)
                skey[pos] = ((unsigned long long)(~u) << 32) | (unsigned)i;
        }
    }
    __syncthreads();
    int cnt = s_cnt < 4096 ? s_cnt : 4096;
    for (int i = tid; i < 4096; i += 1024)
        if (i >= cnt) skey[i] = 0xFFFFFFFFFFFFFFFFull;
    __syncthreads();

    for (int k = 2; k <= 4096; k <<= 1) {
        for (int j = k >> 1; j > 0; j >>= 1) {
            #pragma unroll
            for (int l = 0; l < 4; l++) {
                int i = tid + l * 1024;
                int ixj = i ^ j;
                if (ixj > i) {
                    bool up = ((i & k) == 0);
                    unsigned long long a = skey[i], c = skey[ixj];
                    if (up ? (a > c) : (a < c)) { skey[i] = c; skey[ixj] = a; }
                }
            }
            __syncthreads();
        }
    }

    if (tid < NMS_CAND) {
        unsigned long long key = skey[tid];
        int idx = (int)(unsigned)key;
        float s = __uint_as_float(~(unsigned)(key >> 32));
        int g = b * HW + idx;
        int dst = b * NMS_CAND + tid;
        g_cand_sc[dst] = s;
        g_cand_lab[dst] = g_label[g];
        #pragma unroll
        for (int q = 0; q < 4; q++)
            g_cand_box[dst * 4 + q] = g_boxes[(size_t)g * 4 + q];
    }
}

// ---------------- NMS ----------------
__global__ void nms_mask_k() {
    int i = blockIdx.x;
    int b = blockIdx.y;
    int j = threadIdx.x;
    const float* bi = &g_cand_box[(b * NMS_CAND + i) * 4];
    float ix1 = bi[0], iy1 = bi[1], ix2 = bi[2], iy2 = bi[3];
    float ai = fmaxf(ix2 - ix1, 0.f) * fmaxf(iy2 - iy1, 0.f);
    bool pred = false;
    if (j < NMS_CAND && j > i) {
        const float* bj = &g_cand_box[(b * NMS_CAND + j) * 4];
        float aj = fmaxf(bj[2] - bj[0], 0.f) * fmaxf(bj[3] - bj[1], 0.f);
        float xx1 = fmaxf(ix1, bj[0]), yy1 = fmaxf(iy1, bj[1]);
        float xx2 = fminf(ix2, bj[2]), yy2 = fminf(iy2, bj[3]);
        float iw = fmaxf(xx2 - xx1, 0.f), ih = fmaxf(yy2 - yy1, 0.f);
        float inter = iw * ih;
        float iou = inter / (ai + aj - inter + 1e-6f);
        pred = iou > 0.65f;
    }
    unsigned m = __ballot_sync(0xffffffffu, pred);
    if ((j & 31) == 0)
        g_mask[((size_t)(b * NMS_CAND + i)) * 32 + (j >> 5)] = m;
}

__global__ void nms_reduce_k() {
    extern __shared__ unsigned smask[];
    int b = blockIdx.x;
    for (int t = threadIdx.x; t < NMS_CAND * 32; t += 1024)
        smask[t] = g_mask[(size_t)b * NMS_CAND * 32 + t];
    __syncthreads();
    if (threadIdx.x < 32) {
        int lane = threadIdx.x;
        unsigned removed = 0u;
        for (int i = 0; i < NMS_CAND; i++) {
            unsigned rw = __shfl_sync(0xffffffffu, removed, i >> 5);
            if (!((rw >> (i & 31)) & 1u))
                removed |= smask[i * 32 + lane];
        }
        g_keep[b * 32 + lane] = ~removed;
    }
}

// ---------------- final select ----------------
__global__ void select_k(float* __restrict__ out) {
    __shared__ int ps[1024];
    __shared__ int s_total;
    int b = blockIdx.x;
    int tid = threadIdx.x;
    int kept = 0;
    if (tid < NMS_CAND)
        kept = (g_keep[b * 32 + (tid >> 5)] >> (tid & 31)) & 1;
    ps[tid] = kept;
    __syncthreads();
    for (int off = 1; off < 1024; off <<= 1) {
        int v = (tid >= off) ? ps[tid - off] : 0;
        __syncthreads();
        ps[tid] += v;
        __syncthreads();
    }
    if (tid == 1023) s_total = ps[1023];
    __syncthreads();
    int total = s_total;
    if (tid < NMS_CAND) {
        int excl = ps[tid] - kept;
        int pos = kept ? excl : total + (tid - excl);
        if (pos < MAX_DET) {
            int src = b * NMS_CAND + tid;
            out[(b * MAX_DET + pos) * 4 + 0] = g_cand_box[src * 4 + 0];
            out[(b * MAX_DET + pos) * 4 + 1] = g_cand_box[src * 4 + 1];
            out[(b * MAX_DET + pos) * 4 + 2] = g_cand_box[src * 4 + 2];
            out[(b * MAX_DET + pos) * 4 + 3] = g_cand_box[src * 4 + 3];
            out[BB * MAX_DET * 4 + b * MAX_DET + pos] = kept ? g_cand_sc[src] : 0.f;
            out[BB * MAX_DET * 5 + b * MAX_DET + pos] = (float)g_cand_lab[src];
        }
    }
}

// ---------------- launch ----------------
extern "C" void kernel_launch(void* const* d_in, const int* in_sizes, int n_in,
                              void* d_out, int out_size) {
    (void)in_sizes; (void)n_in; (void)out_size;
    const float* feat = (const float*)d_in[0];
    const float* cls_w_in  = (const float*)d_in[1];
    const float* cls_b_in  = (const float*)d_in[2];
    const float* cls_w_hid = (const float*)d_in[3];
    const float* cls_b_hid = (const float*)d_in[4];
    const float* cls_w_out = (const float*)d_in[5];
    const float* cls_b_out = (const float*)d_in[6];
    const float* obj_w_in  = (const float*)d_in[7];
    const float* obj_b_in  = (const float*)d_in[8];
    const float* obj_w_hid = (const float*)d_in[9];
    const float* obj_b_hid = (const float*)d_in[10];
    const float* obj_w_out = (const float*)d_in[11];
    const float* obj_b_out = (const float*)d_in[12];
    const float* box_w_in  = (const float*)d_in[13];
    const float* box_b_in  = (const float*)d_in[14];
    const float* box_w_hid = (const float*)d_in[15];
    const float* box_b_hid = (const float*)d_in[16];
    const float* box_w_out = (const float*)d_in[17];
    const float* box_b_out = (const float*)d_in[18];
    float* out = (float*)d_out;

    const int comp_smem = (8192 + 256 * 33) * (int)sizeof(float);   // 66560 B
    const int fdec_smem = (STG16 + 1712 + 128 * 97) * (int)sizeof(float);
    cudaFuncSetAttribute(comp_k, cudaFuncAttributeMaxDynamicSharedMemorySize, comp_smem);
    cudaFuncSetAttribute(fdec_k, cudaFuncAttributeMaxDynamicSharedMemorySize, fdec_smem);
    cudaFuncSetAttribute(nms_reduce_k, cudaFuncAttributeMaxDynamicSharedMemorySize, 131072);

    // 0) prologue: compose the entire network into WF[96][256], bF[96]
    comp_k<<<dim3(8, 8, 6), 256, comp_smem>>>(0, cls_w_hid, obj_w_hid, box_w_hid,
                                              cls_w_in, obj_w_in, box_w_in);
    biasv_k<<<6, 256>>>(0, cls_w_hid, obj_w_hid, box_w_hid,
                        cls_b_hid, obj_b_hid, box_b_hid,
                        cls_b_in, obj_b_in, box_b_in);
    comp_k<<<dim3(8, 8, 3), 256, comp_smem>>>(1, cls_w_hid, obj_w_hid, box_w_hid,
                                              cls_w_in, obj_w_in, box_w_in);
    biasv_k<<<3, 256>>>(1, cls_w_hid, obj_w_hid, box_w_hid,
                        cls_b_hid, obj_b_hid, box_b_hid,
                        cls_b_in, obj_b_in, box_b_in);
    comp_k<<<dim3(8, 8, 3), 256, comp_smem>>>(2, cls_w_hid, obj_w_hid, box_w_hid,
                                              cls_w_in, obj_w_in, box_w_in);
    biasv_k<<<3, 256>>>(2, cls_w_hid, obj_w_hid, box_w_hid,
                        cls_b_hid, obj_b_hid, box_b_hid,
                        cls_b_in, obj_b_in, box_b_in);
    wf_k<<<96, 256>>>(cls_w_out, cls_b_out, obj_w_out, obj_b_out, box_w_out, box_b_out);

    // 1) fused full-network GEMM + decode
    fdec_k<<<MPIX / 128, 256, fdec_smem>>>(feat);

    // 2) exact per-batch top-1000
    topk_k<<<BB, 1024>>>();

    // 3) NMS
    nms_mask_k<<<dim3(NMS_CAND, BB), 1024>>>();
    nms_reduce_k<<<BB, 1024, NMS_CAND * 32 * (int)sizeof(unsigned)>>>();

    // 4) final top-100 select
    select_k<<<BB, 1024>>>(out);
}

// round 14
// speedup vs baseline: 6.2076x; 1.1308x over previous
#include <cuda_runtime.h>
#include <cstdint>
#include <cstddef>

// ---------------- problem constants ----------------
#define BB 2
#define CC 256
#define HW 16384
#define MPIX 32768
#define NCLS 80
#define NMS_CAND 1000
#define MAX_DET 100
#define STG16 (16 * 132)

// ---------------- scratch ----------------
__device__ float g_WF[96 * 256];     // full weights: rows 0..79 cls, 80..83 box, 84 obj, 85..95 zero
__device__ float g_bF[96];
__device__ float g_score[MPIX];
__device__ int   g_label[MPIX];
__device__ float g_boxes[(size_t)MPIX * 4];
__device__ float g_cand_sc[BB * NMS_CAND];
__device__ int   g_cand_lab[BB * NMS_CAND];
__device__ float g_cand_box[BB * NMS_CAND * 4];
__device__ unsigned g_mask[(size_t)BB * NMS_CAND * 32];
__device__ unsigned g_keep[BB * 32];

__device__ __forceinline__ float sigmoidf_(float x) { return 1.f / (1.f + expf(-x)); }

// ---------------- single-kernel full-network composition (row-parallel, left-assoc) ----------------
// logits = W_out (I+W3)(I+W2)(I+W1)(I+W0) (W_in x + b_in) + accumulated biases.
// Each block owns 4 output rows; rows evolve independently: T <- T(I+W_l), tb += T b_l.
__global__ void __launch_bounds__(256) wfull_k(
    const float* __restrict__ cwin, const float* __restrict__ cbin,
    const float* __restrict__ cwh,  const float* __restrict__ cbh,
    const float* __restrict__ cwo,  const float* __restrict__ cbo,
    const float* __restrict__ owin, const float* __restrict__ obin,
    const float* __restrict__ owh,  const float* __restrict__ obh,
    const float* __restrict__ owo,  const float* __restrict__ obo,
    const float* __restrict__ bwin, const float* __restrict__ bbin,
    const float* __restrict__ bwh,  const float* __restrict__ bbh,
    const float* __restrict__ bwo,  const float* __restrict__ bbo)
{
    __shared__ float T[2][4][256];
    __shared__ float tb[4];
    const int bid = blockIdx.x;   // 0..23 -> slots 4*bid..4*bid+3
    const int t = threadIdx.x;    // 256
    const int lane = t & 31;

    // head selection (pad rows are zero and chain-invariant, so any chain works for them)
    const float *Whid, *bhid, *Win, *binp;
    if (bid < 20)      { Whid = cwh; bhid = cbh; Win = cwin; binp = cbin; }
    else if (bid == 20){ Whid = bwh; bhid = bbh; Win = bwin; binp = bbin; }
    else               { Whid = owh; bhid = obh; Win = owin; binp = obin; }

    // init T rows + tb from out-layer
    #pragma unroll
    for (int r = 0; r < 4; r++) {
        int s = bid * 4 + r;
        float v = 0.f;
        if (s < 80)        v = cwo[(size_t)s * 256 + t];
        else if (s < 84)   v = bwo[(size_t)(s - 80) * 256 + t];
        else if (s == 84)  v = owo[t];
        T[0][r][t] = v;
    }
    if (t < 4) {
        int s = bid * 4 + t;
        float bv = 0.f;
        if (s < 80)        bv = cbo[s];
        else if (s < 84)   bv = bbo[s - 80];
        else if (s == 84)  bv = obo[0];
        tb[t] = bv;
    }
    __syncthreads();

    int cur = 0;
    // absorb hidden layers from the output side: l = 3,2,1,0
    for (int l = 3; l >= 0; l--) {
        const float* W = Whid + (size_t)l * 65536;
        const float* bl = bhid + l * 256;
        // tb[r] += sum_k T[r][k] * bl[k]   (using current T)
        float blv = bl[t];
        #pragma unroll
        for (int r = 0; r < 4; r++) {
            float pv = T[cur][r][t] * blv;
            #pragma unroll
            for (int off = 16; off > 0; off >>= 1)
                pv += __shfl_xor_sync(0xffffffffu, pv, off);
            if (lane == 0) atomicAdd(&tb[r], pv);
        }
        // T <- T (I + W):  T_new[r][k] = T[r][k] + sum_j T[r][j] * W[j][k]
        float acc0 = 0.f, acc1 = 0.f, acc2 = 0.f, acc3 = 0.f;
        #pragma unroll 8
        for (int j = 0; j < 256; j++) {
            float w = W[(size_t)j * 256 + t];
            acc0 = fmaf(T[cur][0][j], w, acc0);
            acc1 = fmaf(T[cur][1][j], w, acc1);
            acc2 = fmaf(T[cur][2][j], w, acc2);
            acc3 = fmaf(T[cur][3][j], w, acc3);
        }
        T[cur ^ 1][0][t] = T[cur][0][t] + acc0;
        T[cur ^ 1][1][t] = T[cur][1][t] + acc1;
        T[cur ^ 1][2][t] = T[cur][2][t] + acc2;
        T[cur ^ 1][3][t] = T[cur][3][t] + acc3;
        __syncthreads();
        cur ^= 1;
    }

    // tb[r] += sum_k T[r][k] * b_in[k]
    {
        float bv = binp[t];
        #pragma unroll
        for (int r = 0; r < 4; r++) {
            float pv = T[cur][r][t] * bv;
            #pragma unroll
            for (int off = 16; off > 0; off >>= 1)
                pv += __shfl_xor_sync(0xffffffffu, pv, off);
            if (lane == 0) atomicAdd(&tb[r], pv);
        }
    }
    // WF rows = T * W_in
    float acc0 = 0.f, acc1 = 0.f, acc2 = 0.f, acc3 = 0.f;
    #pragma unroll 8
    for (int j = 0; j < 256; j++) {
        float w = Win[(size_t)j * 256 + t];
        acc0 = fmaf(T[cur][0][j], w, acc0);
        acc1 = fmaf(T[cur][1][j], w, acc1);
        acc2 = fmaf(T[cur][2][j], w, acc2);
        acc3 = fmaf(T[cur][3][j], w, acc3);
    }
    g_WF[(size_t)(bid * 4 + 0) * 256 + t] = acc0;
    g_WF[(size_t)(bid * 4 + 1) * 256 + t] = acc1;
    g_WF[(size_t)(bid * 4 + 2) * 256 + t] = acc2;
    g_WF[(size_t)(bid * 4 + 3) * 256 + t] = acc3;
    __syncthreads();
    if (t < 4) g_bF[bid * 4 + t] = tb[t];
}

// ---------------- fused full-network GEMM + decode ----------------
__global__ void __launch_bounds__(256) fdec_k(const float* __restrict__ feat) {
    extern __shared__ __align__(16) float sm[];
    float* As   = sm;                    // [16][132]
    float* Bsw  = sm + STG16;            // [16][100]
    float* sbias = sm + STG16 + 1600;    // 112
    float* slog = sm + STG16 + 1712;     // [128][97]

    const int m0 = blockIdx.x * 128;
    const int b = m0 >> 14;
    const int mm = m0 & (HW - 1);
    const int tid = threadIdx.x;
    const int tx = tid & 15, ty = tid >> 4;

    if (tid < 96) sbias[tid] = g_bF[tid];

    float acc[8][6];
    #pragma unroll
    for (int i = 0; i < 8; i++)
        #pragma unroll
        for (int j = 0; j < 6; j++) acc[i][j] = 0.f;

    #pragma unroll 1
    for (int p = 0; p < 16; p++) {
        __syncthreads();
        #pragma unroll
        for (int lq = 0; lq < 2; lq++) {
            int idx = tid + lq * 256;
            int k = idx >> 5, c4 = idx & 31;
            *(float4*)&As[k * 132 + c4 * 4] =
                *(const float4*)(feat + ((size_t)(b * CC + p * 16 + k)) * HW + mm + c4 * 4);
        }
        #pragma unroll
        for (int lq = 0; lq < 6; lq++) {
            int idx = tid + lq * 256;
            int k = idx & 15, slot = idx >> 4;
            Bsw[k * 100 + slot] = g_WF[(size_t)slot * 256 + p * 16 + k];
        }
        __syncthreads();

        #pragma unroll
        for (int kk = 0; kk < 16; kk++) {
            float4 a0 = *(const float4*)&As[kk * 132 + ty * 8];
            float4 a1 = *(const float4*)&As[kk * 132 + ty * 8 + 4];
            float a[8] = {a0.x, a0.y, a0.z, a0.w, a1.x, a1.y, a1.z, a1.w};
            float bv[6];
            #pragma unroll
            for (int j = 0; j < 6; j++) bv[j] = Bsw[kk * 100 + tx + 16 * j];
            #pragma unroll
            for (int i = 0; i < 8; i++)
                #pragma unroll
                for (int j = 0; j < 6; j++)
                    acc[i][j] = fmaf(a[i], bv[j], acc[i][j]);
        }
    }

    __syncthreads();
    #pragma unroll
    for (int i = 0; i < 8; i++)
        #pragma unroll
        for (int j = 0; j < 6; j++) {
            int col = tx + 16 * j;
            slog[(ty * 8 + i) * 97 + col] = acc[i][j] + sbias[col];
        }
    __syncthreads();

    if (tid < 128) {
        const float* lg = &slog[tid * 97];
        float objp = sigmoidf_(lg[84]);
        float best = -1.f; int bl = 0;
        #pragma unroll 4
        for (int c = 0; c < NCLS; c++) {
            float pr = sigmoidf_(lg[c]) * objp;
            if (pr > best) { best = pr; bl = c; }
        }
        int n = m0 + tid;
        g_score[n] = best;
        g_label[n] = bl;
        int hw = n & (HW - 1);
        int h = hw >> 7, w = hw & 127;
        float px = (w + 0.5f) * 8.f;
        float py = (h + 0.5f) * 8.f;
        float l = expf(lg[80]) * 8.f;
        float t = expf(lg[81]) * 8.f;
        float r = expf(lg[82]) * 8.f;
        float d = expf(lg[83]) * 8.f;
        g_boxes[(size_t)n * 4 + 0] = px - l;
        g_boxes[(size_t)n * 4 + 1] = py - t;
        g_boxes[(size_t)n * 4 + 2] = px + r;
        g_boxes[(size_t)n * 4 + 3] = py + d;
    }
}

// ---------------- exact top-1000: warp-aggregated histograms + compact + bitonic ----------------
__global__ void topk_k() {
    __shared__ int hist[256];
    __shared__ int s_b1, s_n1, s_thr, s_cnt;
    __shared__ unsigned long long skey[4096];
    int b = blockIdx.x;
    int tid = threadIdx.x;   // 1024
    int lane = tid & 31;

    if (tid < 256) hist[tid] = 0;
    __syncthreads();
    for (int i = tid; i < HW; i += 1024) {
        unsigned u = __float_as_uint(g_score[b * HW + i]);
        int bin = u >> 24;
        unsigned mm = __match_any_sync(0xffffffffu, bin);
        if (lane == (__ffs(mm) - 1)) atomicAdd(&hist[bin], __popc(mm));
    }
    __syncthreads();
    if (tid == 0) {
        int acc = 0; int bin = 255;
        for (; bin > 0; bin--) { if (acc + hist[bin] >= NMS_CAND) break; acc += hist[bin]; }
        s_b1 = bin; s_n1 = acc;
    }
    __syncthreads();
    int b1 = s_b1, n1 = s_n1;
    if (tid < 256) hist[tid] = 0;
    __syncthreads();
    for (int i = tid; i < HW; i += 1024) {
        unsigned u = __float_as_uint(g_score[b * HW + i]);
        bool sel = ((int)(u >> 24) == b1);
        unsigned active = __ballot_sync(0xffffffffu, sel);
        if (sel) {
            int bin2 = (u >> 16) & 255;
            unsigned mm = __match_any_sync(active, bin2);
            if (lane == (__ffs(mm) - 1)) atomicAdd(&hist[bin2], __popc(mm));
        }
    }
    __syncthreads();
    if (tid == 0) {
        int acc = n1; int bin = 255;
        for (; bin > 0; bin--) { if (acc + hist[bin] >= NMS_CAND) break; acc += hist[bin]; }
        s_thr = (b1 << 8) | bin;
        s_cnt = 0;
    }
    __syncthreads();
    unsigned thr = (unsigned)s_thr;
    for (int i = tid; i < HW; i += 1024) {
        unsigned u = __float_as_uint(g_score[b * HW + i]);
        bool pass = (u >> 16) >= thr;
        unsigned bal = __ballot_sync(0xffffffffu, pass);
        int base = 0;
        if (lane == 0 && bal) base = atomicAdd(&s_cnt, __popc(bal));
        base = __shfl_sync(0xffffffffu, base, 0);
        if (pass) {
            int pos = base + __popc(bal & ((1u << lane) - 1u));
            if (pos < 4096)
                skey[pos] = ((unsigned long long)(~u) << 32) | (unsigned)i;
        }
    }
    __syncthreads();
    int cnt = s_cnt < 4096 ? s_cnt : 4096;
    for (int i = tid; i < 4096; i += 1024)
        if (i >= cnt) skey[i] = 0xFFFFFFFFFFFFFFFFull;
    __syncthreads();

    for (int k = 2; k <= 4096; k <<= 1) {
        for (int j = k >> 1; j > 0; j >>= 1) {
            #pragma unroll
            for (int l = 0; l < 4; l++) {
                int i = tid + l * 1024;
                int ixj = i ^ j;
                if (ixj > i) {
                    bool up = ((i & k) == 0);
                    unsigned long long a = skey[i], c = skey[ixj];
                    if (up ? (a > c) : (a < c)) { skey[i] = c; skey[ixj] = a; }
                }
            }
            __syncthreads();
        }
    }

    if (tid < NMS_CAND) {
        unsigned long long key = skey[tid];
        int idx = (int)(unsigned)key;
        float s = __uint_as_float(~(unsigned)(key >> 32));
        int g = b * HW + idx;
        int dst = b * NMS_CAND + tid;
        g_cand_sc[dst] = s;
        g_cand_lab[dst] = g_label[g];
        #pragma unroll
        for (int q = 0; q < 4; q++)
            g_cand_box[dst * 4 + q] = g_boxes[(size_t)g * 4 + q];
    }
}

// ---------------- NMS ----------------
__global__ void nms_mask_k() {
    int i = blockIdx.x;
    int b = blockIdx.y;
    int j = threadIdx.x;
    const float* bi = &g_cand_box[(b * NMS_CAND + i) * 4];
    float ix1 = bi[0], iy1 = bi[1], ix2 = bi[2], iy2 = bi[3];
    float ai = fmaxf(ix2 - ix1, 0.f) * fmaxf(iy2 - iy1, 0.f);
    bool pred = false;
    if (j < NMS_CAND && j > i) {
        const float* bj = &g_cand_box[(b * NMS_CAND + j) * 4];
        float aj = fmaxf(bj[2] - bj[0], 0.f) * fmaxf(bj[3] - bj[1], 0.f);
        float xx1 = fmaxf(ix1, bj[0]), yy1 = fmaxf(iy1, bj[1]);
        float xx2 = fminf(ix2, bj[2]), yy2 = fminf(iy2, bj[3]);
        float iw = fmaxf(xx2 - xx1, 0.f), ih = fmaxf(yy2 - yy1, 0.f);
        float inter = iw * ih;
        float iou = inter / (ai + aj - inter + 1e-6f);
        pred = iou > 0.65f;
    }
    unsigned m = __ballot_sync(0xffffffffu, pred);
    if ((j & 31) == 0)
        g_mask[((size_t)(b * NMS_CAND + i)) * 32 + (j >> 5)] = m;
}

__global__ void nms_reduce_k() {
    extern __shared__ unsigned smask[];
    int b = blockIdx.x;
    for (int t = threadIdx.x; t < NMS_CAND * 32; t += 1024)
        smask[t] = g_mask[(size_t)b * NMS_CAND * 32 + t];
    __syncthreads();
    if (threadIdx.x < 32) {
        int lane = threadIdx.x;
        unsigned removed = 0u;
        for (int i = 0; i < NMS_CAND; i++) {
            unsigned rw = __shfl_sync(0xffffffffu, removed, i >> 5);
            if (!((rw >> (i & 31)) & 1u))
                removed |= smask[i * 32 + lane];
        }
        g_keep[b * 32 + lane] = ~removed;
    }
}

// ---------------- final select ----------------
__global__ void select_k(float* __restrict__ out) {
    __shared__ int ps[1024];
    __shared__ int s_total;
    int b = blockIdx.x;
    int tid = threadIdx.x;
    int kept = 0;
    if (tid < NMS_CAND)
        kept = (g_keep[b * 32 + (tid >> 5)] >> (tid & 31)) & 1;
    ps[tid] = kept;
    __syncthreads();
    for (int off = 1; off < 1024; off <<= 1) {
        int v = (tid >= off) ? ps[tid - off] : 0;
        __syncthreads();
        ps[tid] += v;
        __syncthreads();
    }
    if (tid == 1023) s_total = ps[1023];
    __syncthreads();
    int total = s_total;
    if (tid < NMS_CAND) {
        int excl = ps[tid] - kept;
        int pos = kept ? excl : total + (tid - excl);
        if (pos < MAX_DET) {
            int src = b * NMS_CAND + tid;
            out[(b * MAX_DET + pos) * 4 + 0] = g_cand_box[src * 4 + 0];
            out[(b * MAX_DET + pos) * 4 + 1] = g_cand_box[src * 4 + 1];
            out[(b * MAX_DET + pos) * 4 + 2] = g_cand_box[src * 4 + 2];
            out[(b * MAX_DET + pos) * 4 + 3] = g_cand_box[src * 4 + 3];
            out[BB * MAX_DET * 4 + b * MAX_DET + pos] = kept ? g_cand_sc[src] : 0.f;
            out[BB * MAX_DET * 5 + b * MAX_DET + pos] = (float)g_cand_lab[src];
        }
    }
}

// ---------------- launch ----------------
extern "C" void kernel_launch(void* const* d_in, const int* in_sizes, int n_in,
                              void* d_out, int out_size) {
    (void)in_sizes; (void)n_in; (void)out_size;
    const float* feat = (const float*)d_in[0];
    const float* cls_w_in  = (const float*)d_in[1];
    const float* cls_b_in  = (const float*)d_in[2];
    const float* cls_w_hid = (const float*)d_in[3];
    const float* cls_b_hid = (const float*)d_in[4];
    const float* cls_w_out = (const float*)d_in[5];
    const float* cls_b_out = (const float*)d_in[6];
    const float* obj_w_in  = (const float*)d_in[7];
    const float* obj_b_in  = (const float*)d_in[8];
    const float* obj_w_hid = (const float*)d_in[9];
    const float* obj_b_hid = (const float*)d_in[10];
    const float* obj_w_out = (const float*)d_in[11];
    const float* obj_b_out = (const float*)d_in[12];
    const float* box_w_in  = (const float*)d_in[13];
    const float* box_b_in  = (const float*)d_in[14];
    const float* box_w_hid = (const float*)d_in[15];
    const float* box_b_hid = (const float*)d_in[16];
    const float* box_w_out = (const float*)d_in[17];
    const float* box_b_out = (const float*)d_in[18];
    float* out = (float*)d_out;

    const int fdec_smem = (STG16 + 1712 + 128 * 97) * (int)sizeof(float);
    cudaFuncSetAttribute(fdec_k, cudaFuncAttributeMaxDynamicSharedMemorySize, fdec_smem);
    cudaFuncSetAttribute(nms_reduce_k, cudaFuncAttributeMaxDynamicSharedMemorySize, 131072);

    // 0) single-kernel full-network composition -> WF[96][256], bF[96]
    wfull_k<<<24, 256>>>(cls_w_in, cls_b_in, cls_w_hid, cls_b_hid, cls_w_out, cls_b_out,
                         obj_w_in, obj_b_in, obj_w_hid, obj_b_hid, obj_w_out, obj_b_out,
                         box_w_in, box_b_in, box_w_hid, box_b_hid, box_w_out, box_b_out);

    // 1) fused full-network GEMM + decode
    fdec_k<<<MPIX / 128, 256, fdec_smem>>>(feat);

    // 2) exact per-batch top-1000
    topk_k<<<BB, 1024>>>();

    // 3) NMS
    nms_mask_k<<<dim3(NMS_CAND, BB), 1024>>>();
    nms_reduce_k<<<BB, 1024, NMS_CAND * 32 * (int)sizeof(unsigned)>>>();

    // 4) final top-100 select
    select_k<<<BB, 1024>>>(out);
}